// round 1
// baseline (speedup 1.0000x reference)
#include <cuda_runtime.h>

#define DM   1024
#define NH   16
#define DKH  64
#define BB   4
#define SS   2048
#define MROWS (BB*SS)   // 8192

// Scratch (allocation-free rule: device globals)
__device__ float g_Q[BB*NH*SS*DKH];
__device__ float g_K[BB*NH*SS*DKH];
__device__ float g_V[BB*NH*SS*DKH];
__device__ float g_AO[BB*SS*DM];

// ---------------------------------------------------------------------------
// GEMM: C[m,n] = sum_k A[m,k] * W[n,k] + bias[n]
// BM=128, BN=64, BK=16, 256 threads, 8x4 per-thread micro-tile.
// SCATTER=1 writes into [B,H,S,dk] layout (for Q/K/V); SCATTER=0 row-major.
// blockIdx.z selects among up to 3 (W, bias, C) triples (fused QKV).
// ---------------------------------------------------------------------------
template<int SCATTER>
__global__ void __launch_bounds__(256) gemm_bias_kernel(
    const float* __restrict__ A,
    const float* __restrict__ W0, const float* __restrict__ b0, float* __restrict__ C0,
    const float* __restrict__ W1, const float* __restrict__ b1, float* __restrict__ C1,
    const float* __restrict__ W2, const float* __restrict__ b2, float* __restrict__ C2)
{
    const float* Wt; const float* bias; float* C;
    const int z = blockIdx.z;
    if (z == 0)      { Wt = W0; bias = b0; C = C0; }
    else if (z == 1) { Wt = W1; bias = b1; C = C1; }
    else             { Wt = W2; bias = b2; C = C2; }

    __shared__ float As[16][128];   // k-major A tile
    __shared__ float Bs[16][64];    // k-major W tile

    const int tid = threadIdx.x;
    const int m0 = blockIdx.x * 128;
    const int n0 = blockIdx.y * 64;
    const int tr = tid >> 4;          // 0..15 -> rows tr*8..tr*8+7
    const int tc = tid & 15;          // 0..15 -> cols tc*4..tc*4+3

    const int ar = tid >> 2;          // 0..63
    const int ak = (tid & 3) << 2;    // 0,4,8,12

    float acc[8][4];
#pragma unroll
    for (int i = 0; i < 8; i++)
#pragma unroll
        for (int j = 0; j < 4; j++) acc[i][j] = 0.f;

    const float* Arow0 = A  + (size_t)(m0 + ar)      * DM;
    const float* Arow1 = A  + (size_t)(m0 + ar + 64) * DM;
    const float* Wrow  = Wt + (size_t)(n0 + ar)      * DM;

    for (int kt = 0; kt < DM; kt += 16) {
        float4 a0 = *(const float4*)(Arow0 + kt + ak);
        float4 a1 = *(const float4*)(Arow1 + kt + ak);
        float4 w0 = *(const float4*)(Wrow  + kt + ak);

        As[ak+0][ar]    = a0.x; As[ak+1][ar]    = a0.y;
        As[ak+2][ar]    = a0.z; As[ak+3][ar]    = a0.w;
        As[ak+0][ar+64] = a1.x; As[ak+1][ar+64] = a1.y;
        As[ak+2][ar+64] = a1.z; As[ak+3][ar+64] = a1.w;
        Bs[ak+0][ar]    = w0.x; Bs[ak+1][ar]    = w0.y;
        Bs[ak+2][ar]    = w0.z; Bs[ak+3][ar]    = w0.w;
        __syncthreads();

#pragma unroll
        for (int k = 0; k < 16; k++) {
            float xv[8], yv[4];
            *(float4*)&xv[0] = *(const float4*)&As[k][tr*8];
            *(float4*)&xv[4] = *(const float4*)&As[k][tr*8 + 4];
            *(float4*)&yv[0] = *(const float4*)&Bs[k][tc*4];
#pragma unroll
            for (int i = 0; i < 8; i++)
#pragma unroll
                for (int j = 0; j < 4; j++)
                    acc[i][j] = fmaf(xv[i], yv[j], acc[i][j]);
        }
        __syncthreads();
    }

    const int ncol = n0 + tc*4;
    float4 bv = *(const float4*)&bias[ncol];

#pragma unroll
    for (int i = 0; i < 8; i++) {
        const int m = m0 + tr*8 + i;
        float4 r;
        r.x = acc[i][0] + bv.x;
        r.y = acc[i][1] + bv.y;
        r.z = acc[i][2] + bv.z;
        r.w = acc[i][3] + bv.w;
        if (SCATTER) {
            // [B,S] row m -> (b, s); feature ncol -> (h, dc). Write [B,H,S,dk].
            const int bidx = m >> 11;
            const int s    = m & 2047;
            const int h    = ncol >> 6;
            const int dc   = ncol & 63;
            *(float4*)&C[((size_t)((bidx*NH + h)*SS + s) << 6) + dc] = r;
        } else {
            *(float4*)&C[(size_t)m * DM + ncol] = r;
        }
    }
}

// ---------------------------------------------------------------------------
// Flash attention (fp32): one CTA = 64 q rows of one (b,h). dk = 64.
// Online softmax, causal + pad mask, P staged via smem for the O-GEMM.
// Dynamic smem: QsT | KsT | Vs | PsT, each 64*64 floats (64 KB total).
// ---------------------------------------------------------------------------
__global__ void __launch_bounds__(256) flash_kernel(const int* __restrict__ pad)
{
    extern __shared__ float sm[];
    float* QsT = sm;            // [d][r]
    float* KsT = sm + 4096;     // [d][c]
    float* Vs  = sm + 8192;     // [c][dc]
    float* PsT = sm + 12288;    // [c][r]
    __shared__ float padm[64];

    const int tid = threadIdx.x;
    const int bh  = blockIdx.x;                 // 0..63
    const int qt  = (gridDim.y - 1) - blockIdx.y; // heavy tiles first
    const int b   = bh >> 4;
    const int h   = bh & 15;
    const int qi0 = qt * 64;

    const int tr = tid >> 4, tc = tid & 15;
    const int lr = tid >> 2;                    // loader row 0..63
    const int lq = (tid & 3) * 16;              // loader col base (16 cols/thread)

    // Load Q transposed into QsT[d][r]
    {
        const float* Qg = g_Q + ((size_t)bh * SS + qi0) * DKH + (size_t)lr * DKH;
#pragma unroll
        for (int q4 = 0; q4 < 16; q4 += 4) {
            float4 v = *(const float4*)(Qg + lq + q4);
            QsT[(lq+q4+0)*64 + lr] = v.x;
            QsT[(lq+q4+1)*64 + lr] = v.y;
            QsT[(lq+q4+2)*64 + lr] = v.z;
            QsT[(lq+q4+3)*64 + lr] = v.w;
        }
    }

    float mrow[4], lrow[4], acc[4][4];
#pragma unroll
    for (int i = 0; i < 4; i++) {
        mrow[i] = -1e30f; lrow[i] = 0.f;
#pragma unroll
        for (int j = 0; j < 4; j++) acc[i][j] = 0.f;
    }

    for (int jt = 0; jt <= qt; jt++) {
        __syncthreads();   // protect K/V/P smem reuse from previous iteration
        const int kj0 = jt * 64;
        {
            const float* Kg = g_K + ((size_t)bh * SS + kj0) * DKH + (size_t)lr * DKH;
            const float* Vg = g_V + ((size_t)bh * SS + kj0) * DKH + (size_t)lr * DKH;
#pragma unroll
            for (int q4 = 0; q4 < 16; q4 += 4) {
                float4 v = *(const float4*)(Kg + lq + q4);
                KsT[(lq+q4+0)*64 + lr] = v.x;
                KsT[(lq+q4+1)*64 + lr] = v.y;
                KsT[(lq+q4+2)*64 + lr] = v.z;
                KsT[(lq+q4+3)*64 + lr] = v.w;
                float4 vv = *(const float4*)(Vg + lq + q4);
                *(float4*)&Vs[lr*64 + lq + q4] = vv;
            }
            if (tid < 64) padm[tid] = (pad[b*SS + kj0 + tid] == 1) ? 1.f : 0.f;
        }
        __syncthreads();

        // S = Q K^T (4x4 per thread)
        float sv[4][4];
#pragma unroll
        for (int i = 0; i < 4; i++)
#pragma unroll
            for (int j = 0; j < 4; j++) sv[i][j] = 0.f;

#pragma unroll 4
        for (int d = 0; d < 64; d++) {
            float4 qa = *(const float4*)&QsT[d*64 + tr*4];
            float4 kb = *(const float4*)&KsT[d*64 + tc*4];
            float qv[4] = {qa.x, qa.y, qa.z, qa.w};
            float kv[4] = {kb.x, kb.y, kb.z, kb.w};
#pragma unroll
            for (int i = 0; i < 4; i++)
#pragma unroll
                for (int j = 0; j < 4; j++)
                    sv[i][j] = fmaf(qv[i], kv[j], sv[i][j]);
        }

        // Online softmax per row (rows tr*4+i; reduce across 16 tc lanes)
#pragma unroll
        for (int i = 0; i < 4; i++) {
            const int qi = qi0 + tr*4 + i;
            float rmax = -1e30f;
#pragma unroll
            for (int j = 0; j < 4; j++) {
                const int kj = kj0 + tc*4 + j;
                float s = sv[i][j] * 0.125f;     // 1/sqrt(64)
                const bool masked = (kj > qi) || (padm[tc*4+j] != 0.f);
                s = masked ? -1e30f : s;
                sv[i][j] = s;
                rmax = fmaxf(rmax, s);
            }
#pragma unroll
            for (int o = 8; o >= 1; o >>= 1)
                rmax = fmaxf(rmax, __shfl_xor_sync(0xffffffffu, rmax, o));
            const float mnew  = fmaxf(mrow[i], rmax);
            const float alpha = __expf(mrow[i] - mnew);
            float p[4];
            float rsum = 0.f;
#pragma unroll
            for (int j = 0; j < 4; j++) {
                const float pj = (sv[i][j] <= -1e30f) ? 0.f : __expf(sv[i][j] - mnew);
                p[j] = pj; rsum += pj;
            }
#pragma unroll
            for (int o = 8; o >= 1; o >>= 1)
                rsum += __shfl_xor_sync(0xffffffffu, rsum, o);
            lrow[i] = lrow[i] * alpha + rsum;
            mrow[i] = mnew;
#pragma unroll
            for (int j = 0; j < 4; j++) {
                acc[i][j] *= alpha;
                PsT[(tc*4+j)*64 + tr*4 + i] = p[j];
            }
        }
        __syncthreads();

        // O += P V (contract over c)
#pragma unroll 4
        for (int c = 0; c < 64; c++) {
            float4 pa = *(const float4*)&PsT[c*64 + tr*4];
            float4 vb = *(const float4*)&Vs[c*64 + tc*4];
            float pv[4] = {pa.x, pa.y, pa.z, pa.w};
            float vv[4] = {vb.x, vb.y, vb.z, vb.w};
#pragma unroll
            for (int i = 0; i < 4; i++)
#pragma unroll
                for (int j = 0; j < 4; j++)
                    acc[i][j] = fmaf(pv[i], vv[j], acc[i][j]);
        }
    }

    // Epilogue: normalize, write [B,S,D] (heads concatenated)
#pragma unroll
    for (int i = 0; i < 4; i++) {
        const float inv = (lrow[i] > 0.f) ? (1.f / lrow[i]) : 0.f;
        const int q = qi0 + tr*4 + i;
        float4 r = make_float4(acc[i][0]*inv, acc[i][1]*inv, acc[i][2]*inv, acc[i][3]*inv);
        *(float4*)&g_AO[((size_t)(b*SS + q)) * DM + h*DKH + tc*4] = r;
    }
}

// ---------------------------------------------------------------------------
extern "C" void kernel_launch(void* const* d_in, const int* in_sizes, int n_in,
                              void* d_out, int out_size)
{
    (void)in_sizes; (void)n_in; (void)out_size;
    const float* x   = (const float*)d_in[0];
    const int*   pad = (const int*)  d_in[1];
    const float* Wq  = (const float*)d_in[2];
    const float* bq  = (const float*)d_in[3];
    const float* Wk  = (const float*)d_in[4];
    const float* bk  = (const float*)d_in[5];
    const float* Wv  = (const float*)d_in[6];
    const float* bv  = (const float*)d_in[7];
    const float* Wo  = (const float*)d_in[8];
    const float* bo  = (const float*)d_in[9];
    float* out = (float*)d_out;

    float *Qp, *Kp, *Vp, *AOp;
    cudaGetSymbolAddress((void**)&Qp,  g_Q);
    cudaGetSymbolAddress((void**)&Kp,  g_K);
    cudaGetSymbolAddress((void**)&Vp,  g_V);
    cudaGetSymbolAddress((void**)&AOp, g_AO);

    cudaFuncSetAttribute(flash_kernel,
                         cudaFuncAttributeMaxDynamicSharedMemorySize, 65536);

    // 1) Fused QKV projection, scattered into [B,H,S,dk]
    gemm_bias_kernel<1><<<dim3(MROWS/128, DM/64, 3), 256>>>(
        x, Wq, bq, Qp, Wk, bk, Kp, Wv, bv, Vp);

    // 2) Causal flash attention -> g_AO in [B,S,D]
    flash_kernel<<<dim3(BB*NH, SS/64), 256, 65536>>>(pad);

    // 3) Output projection -> d_out
    gemm_bias_kernel<0><<<dim3(MROWS/128, DM/64, 1), 256>>>(
        AOp, Wo, bo, out, Wo, bo, out, Wo, bo, out);
}

// round 6
// speedup vs baseline: 1.3823x; 1.3823x over previous
#include <cuda_runtime.h>
#include <cuda_bf16.h>
#include <cstdint>

#define DM   1024
#define NH   16
#define DKH  64
#define BB   4
#define SS   2048
#define MROWS (BB*SS)   // 8192

// ---------------- device scratch (allocation-free rule) ----------------
__device__ float g_Q[BB*NH*SS*DKH];
__device__ float g_K[BB*NH*SS*DKH];
__device__ float g_V[BB*NH*SS*DKH];
__device__ float g_AO[BB*SS*DM];
__device__ __nv_bfloat16 g_xhi[MROWS*DM];
__device__ __nv_bfloat16 g_xlo[MROWS*DM];
__device__ __nv_bfloat16 g_whi[4*DM*DM];
__device__ __nv_bfloat16 g_wlo[4*DM*DM];
__device__ __nv_bfloat16 g_aohi[MROWS*DM];
__device__ __nv_bfloat16 g_aolo[MROWS*DM];

// ---------------- PTX helpers (baseline ISA only: sm_80-class) ----------------
__device__ __forceinline__ uint32_t smem_u32(const void* p) {
    uint32_t a;
    asm("{ .reg .u64 t; cvta.to.shared.u64 t, %1; cvt.u32.u64 %0, t; }" : "=r"(a) : "l"(p));
    return a;
}
__device__ __forceinline__ void cp16(uint32_t dst, const void* src) {
    asm volatile("cp.async.cg.shared.global [%0], [%1], 16;" :: "r"(dst), "l"(src));
}
__device__ __forceinline__ void cp_commit() {
    asm volatile("cp.async.commit_group;" ::: "memory");
}
template<int N> __device__ __forceinline__ void cp_wait() {
    asm volatile("cp.async.wait_group %0;" :: "n"(N) : "memory");
}
__device__ __forceinline__ void ldsm_x4(uint32_t& r0, uint32_t& r1, uint32_t& r2, uint32_t& r3,
                                        uint32_t addr) {
    asm volatile("ldmatrix.sync.aligned.m8n8.x4.shared.b16 {%0,%1,%2,%3}, [%4];"
                 : "=r"(r0), "=r"(r1), "=r"(r2), "=r"(r3) : "r"(addr));
}
__device__ __forceinline__ void mma16816(float* c, const uint32_t* a, const uint32_t* b) {
    asm volatile(
        "mma.sync.aligned.m16n8k16.row.col.f32.bf16.bf16.f32 "
        "{%0,%1,%2,%3}, {%4,%5,%6,%7}, {%8,%9}, {%0,%1,%2,%3};"
        : "+f"(c[0]), "+f"(c[1]), "+f"(c[2]), "+f"(c[3])
        : "r"(a[0]), "r"(a[1]), "r"(a[2]), "r"(a[3]), "r"(b[0]), "r"(b[1]));
}

// ---------------------------------------------------------------------------
// split: hi = bf16(x), lo = bf16(x - hi)   (4 elems/thread)
// ---------------------------------------------------------------------------
__global__ void split_kernel(const float* __restrict__ src,
                             __nv_bfloat16* __restrict__ hi,
                             __nv_bfloat16* __restrict__ lo, int n4)
{
    int i = blockIdx.x * blockDim.x + threadIdx.x;
    if (i < n4) {
        float4 v = *(const float4*)(src + i * 4);
        __nv_bfloat16 h0 = __float2bfloat16(v.x);
        __nv_bfloat16 h1 = __float2bfloat16(v.y);
        __nv_bfloat16 h2 = __float2bfloat16(v.z);
        __nv_bfloat16 h3 = __float2bfloat16(v.w);
        __nv_bfloat162 H0{h0, h1}, H1{h2, h3};
        __nv_bfloat162 L0{__float2bfloat16(v.x - __bfloat162float(h0)),
                          __float2bfloat16(v.y - __bfloat162float(h1))};
        __nv_bfloat162 L1{__float2bfloat16(v.z - __bfloat162float(h2)),
                          __float2bfloat16(v.w - __bfloat162float(h3))};
        *(uint2*)(hi + i * 4) = make_uint2(*(uint32_t*)&H0, *(uint32_t*)&H1);
        *(uint2*)(lo + i * 4) = make_uint2(*(uint32_t*)&L0, *(uint32_t*)&L1);
    }
}

// ---------------------------------------------------------------------------
// HMMA GEMM: C[m,n] = sum_k A[m,k]*W[n,k] + bias[n]  (3-term bf16 split)
// CTA 128x128, BK=32, 256 threads (8 warps, 2m x 4n), cp.async double buffer.
// SCATTER=1 writes [B,H,S,dk]; SCATTER=0 row-major [M,DM].
// ---------------------------------------------------------------------------
#define BKG    32
#define NCHK   (DM / BKG)         // 32
#define ROWB   80                 // padded smem row stride (bytes), 32 bf16 + 16B pad
#define TILEB  (128 * ROWB)       // 10240
#define STAGEB (4 * TILEB)        // Ahi, Alo, Whi, Wlo
#define GSMEM  (2 * STAGEB)       // 81920

template<int SCATTER>
__global__ void __launch_bounds__(256) mma_gemm_kernel(
    const __nv_bfloat16* __restrict__ Ahi, const __nv_bfloat16* __restrict__ Alo,
    const __nv_bfloat16* __restrict__ Whi, const __nv_bfloat16* __restrict__ Wlo,
    int wbase,
    const float* __restrict__ b0, const float* __restrict__ b1, const float* __restrict__ b2,
    float* __restrict__ C0, float* __restrict__ C1, float* __restrict__ C2)
{
    extern __shared__ char sm[];
    const uint32_t sbase = smem_u32(sm);

    const int tid  = threadIdx.x;
    const int warp = tid >> 5;
    const int lane = tid & 31;

    const int z  = blockIdx.z;
    const float* bias = (z == 0) ? b0 : (z == 1) ? b1 : b2;
    float*       C    = (z == 0) ? C0 : (z == 1) ? C1 : C2;
    const int m0 = blockIdx.x * 128;
    const int n0 = blockIdx.y * 128;
    const int wsel = wbase + z;

    const int warp_m = (warp & 1) * 64;   // 2 warps over m
    const int warp_n = (warp >> 1) * 32;  // 4 warps over n

    // ---- loader mapping: tile = tid>>6 (Ahi,Alo,Whi,Wlo), rows r and r+64 ----
    const int ltile = tid >> 6;
    const int lrow  = tid & 63;
    const __nv_bfloat16* lsrc;
    {
        const size_t woff = (size_t)wsel * DM * DM;
        if      (ltile == 0) lsrc = Ahi + (size_t)(m0 + lrow) * DM;
        else if (ltile == 1) lsrc = Alo + (size_t)(m0 + lrow) * DM;
        else if (ltile == 2) lsrc = Whi + woff + (size_t)(n0 + lrow) * DM;
        else                 lsrc = Wlo + woff + (size_t)(n0 + lrow) * DM;
    }
    const uint32_t sdst0 = sbase + ltile * TILEB + lrow * ROWB;

    auto issue_stage = [&](int c, int s) {
        const int k0 = c * BKG;
        const uint32_t d0 = sdst0 + s * STAGEB;
        const char* p0 = (const char*)(lsrc + k0);
        const char* p1 = (const char*)(lsrc + 64 * DM + k0);
        cp16(d0 +  0, p0 +  0);
        cp16(d0 + 16, p0 + 16);
        cp16(d0 + 32, p0 + 32);
        cp16(d0 + 48, p0 + 48);
        cp16(d0 + 64 * ROWB +  0, p1 +  0);
        cp16(d0 + 64 * ROWB + 16, p1 + 16);
        cp16(d0 + 64 * ROWB + 32, p1 + 32);
        cp16(d0 + 64 * ROWB + 48, p1 + 48);
    };

    // ---- ldmatrix per-lane address bases (within a tile) ----
    // A frag (m16k16): lane -> row warp_m + (lane&15) (+ mi*16), koff (lane>>4)*16B
    const uint32_t a_off = (uint32_t)(warp_m + (lane & 15)) * ROWB + ((lane >> 4) << 4);
    // B frag pair (n16k16 via x4): lanes 0-7: n+0..7,k0 | 8-15: n+0..7,k16B | 16-23: n+8..15,k0 | 24-31: n+8..15,k16B
    const uint32_t b_off = (uint32_t)(warp_n + ((lane & 16) >> 1) + (lane & 7)) * ROWB
                         + ((lane & 8) ? 16u : 0u);

    float acc[4][4][4];
#pragma unroll
    for (int i = 0; i < 4; i++)
#pragma unroll
        for (int j = 0; j < 4; j++)
#pragma unroll
            for (int r = 0; r < 4; r++) acc[i][j][r] = 0.f;

    issue_stage(0, 0);
    cp_commit();

    for (int c = 0; c < NCHK; c++) {
        const int s = c & 1;
        if (c + 1 < NCHK) { issue_stage(c + 1, 1 - s); cp_commit(); cp_wait<1>(); }
        else             { cp_wait<0>(); }
        __syncthreads();

        const uint32_t st   = sbase + s * STAGEB;
        const uint32_t tAhi = st + 0 * TILEB;
        const uint32_t tAlo = st + 1 * TILEB;
        const uint32_t tWhi = st + 2 * TILEB;
        const uint32_t tWlo = st + 3 * TILEB;

#pragma unroll
        for (int ks = 0; ks < 2; ks++) {
            const uint32_t ko = ks * 32;   // 16 bf16 = 32 bytes

            uint32_t bh[4][2], bl[4][2];
#pragma unroll
            for (int bj = 0; bj < 2; bj++) {
                uint32_t r0, r1, r2, r3;
                ldsm_x4(r0, r1, r2, r3, tWhi + b_off + bj * (16 * ROWB) + ko);
                bh[bj*2+0][0] = r0; bh[bj*2+0][1] = r1;
                bh[bj*2+1][0] = r2; bh[bj*2+1][1] = r3;
                ldsm_x4(r0, r1, r2, r3, tWlo + b_off + bj * (16 * ROWB) + ko);
                bl[bj*2+0][0] = r0; bl[bj*2+0][1] = r1;
                bl[bj*2+1][0] = r2; bl[bj*2+1][1] = r3;
            }

            uint32_t a[4][4];
#pragma unroll
            for (int mi = 0; mi < 4; mi++)
                ldsm_x4(a[mi][0], a[mi][1], a[mi][2], a[mi][3],
                        tAhi + a_off + mi * (16 * ROWB) + ko);
#pragma unroll
            for (int mi = 0; mi < 4; mi++)
#pragma unroll
                for (int nj = 0; nj < 4; nj++) {
                    mma16816(acc[mi][nj], a[mi], bh[nj]);
                    mma16816(acc[mi][nj], a[mi], bl[nj]);
                }
#pragma unroll
            for (int mi = 0; mi < 4; mi++)
                ldsm_x4(a[mi][0], a[mi][1], a[mi][2], a[mi][3],
                        tAlo + a_off + mi * (16 * ROWB) + ko);
#pragma unroll
            for (int mi = 0; mi < 4; mi++)
#pragma unroll
                for (int nj = 0; nj < 4; nj++)
                    mma16816(acc[mi][nj], a[mi], bh[nj]);
        }
        __syncthreads();
    }

    // ---- epilogue: bias + store (float2 per half-frag) ----
    const int g = lane >> 2;
    const int t = lane & 3;
#pragma unroll
    for (int mi = 0; mi < 4; mi++) {
#pragma unroll
        for (int nj = 0; nj < 4; nj++) {
            const int n  = n0 + warp_n + nj * 8 + t * 2;
            const float bx = __ldg(bias + n);
            const float by = __ldg(bias + n + 1);
#pragma unroll
            for (int half = 0; half < 2; half++) {
                const int m = m0 + warp_m + mi * 16 + g + half * 8;
                float2 v;
                v.x = acc[mi][nj][half * 2 + 0] + bx;
                v.y = acc[mi][nj][half * 2 + 1] + by;
                if (SCATTER) {
                    const int bidx = m >> 11;
                    const int sidx = m & 2047;
                    const int h    = n >> 6;
                    const int dc   = n & 63;
                    *(float2*)&C[((size_t)((bidx * NH + h) * SS + sidx) << 6) + dc] = v;
                } else {
                    *(float2*)&C[(size_t)m * DM + n] = v;
                }
            }
        }
    }
}

// ---------------------------------------------------------------------------
// Flash attention (fp32), unchanged from the passing R1 baseline.
// ---------------------------------------------------------------------------
__global__ void __launch_bounds__(256) flash_kernel(const int* __restrict__ pad)
{
    extern __shared__ float smf[];
    float* QsT = smf;
    float* KsT = smf + 4096;
    float* Vs  = smf + 8192;
    float* PsT = smf + 12288;
    __shared__ float padm[64];

    const int tid = threadIdx.x;
    const int bh  = blockIdx.x;
    const int qt  = (gridDim.y - 1) - blockIdx.y;
    const int b   = bh >> 4;
    const int h   = bh & 15;
    const int qi0 = qt * 64;

    const int tr = tid >> 4, tc = tid & 15;
    const int lr = tid >> 2;
    const int lq = (tid & 3) * 16;

    {
        const float* Qg = g_Q + ((size_t)bh * SS + qi0) * DKH + (size_t)lr * DKH;
#pragma unroll
        for (int q4 = 0; q4 < 16; q4 += 4) {
            float4 v = *(const float4*)(Qg + lq + q4);
            QsT[(lq+q4+0)*64 + lr] = v.x;
            QsT[(lq+q4+1)*64 + lr] = v.y;
            QsT[(lq+q4+2)*64 + lr] = v.z;
            QsT[(lq+q4+3)*64 + lr] = v.w;
        }
    }

    float mrow[4], lrow[4], acc[4][4];
#pragma unroll
    for (int i = 0; i < 4; i++) {
        mrow[i] = -1e30f; lrow[i] = 0.f;
#pragma unroll
        for (int j = 0; j < 4; j++) acc[i][j] = 0.f;
    }

    for (int jt = 0; jt <= qt; jt++) {
        __syncthreads();
        const int kj0 = jt * 64;
        {
            const float* Kg = g_K + ((size_t)bh * SS + kj0) * DKH + (size_t)lr * DKH;
            const float* Vg = g_V + ((size_t)bh * SS + kj0) * DKH + (size_t)lr * DKH;
#pragma unroll
            for (int q4 = 0; q4 < 16; q4 += 4) {
                float4 v = *(const float4*)(Kg + lq + q4);
                KsT[(lq+q4+0)*64 + lr] = v.x;
                KsT[(lq+q4+1)*64 + lr] = v.y;
                KsT[(lq+q4+2)*64 + lr] = v.z;
                KsT[(lq+q4+3)*64 + lr] = v.w;
                float4 vv = *(const float4*)(Vg + lq + q4);
                *(float4*)&Vs[lr*64 + lq + q4] = vv;
            }
            if (tid < 64) padm[tid] = (pad[b*SS + kj0 + tid] == 1) ? 1.f : 0.f;
        }
        __syncthreads();

        float sv[4][4];
#pragma unroll
        for (int i = 0; i < 4; i++)
#pragma unroll
            for (int j = 0; j < 4; j++) sv[i][j] = 0.f;

#pragma unroll 4
        for (int d = 0; d < 64; d++) {
            float4 qa = *(const float4*)&QsT[d*64 + tr*4];
            float4 kb = *(const float4*)&KsT[d*64 + tc*4];
            float qv[4] = {qa.x, qa.y, qa.z, qa.w};
            float kv[4] = {kb.x, kb.y, kb.z, kb.w};
#pragma unroll
            for (int i = 0; i < 4; i++)
#pragma unroll
                for (int j = 0; j < 4; j++)
                    sv[i][j] = fmaf(qv[i], kv[j], sv[i][j]);
        }

#pragma unroll
        for (int i = 0; i < 4; i++) {
            const int qi = qi0 + tr*4 + i;
            float rmax = -1e30f;
#pragma unroll
            for (int j = 0; j < 4; j++) {
                const int kj = kj0 + tc*4 + j;
                float s = sv[i][j] * 0.125f;
                const bool masked = (kj > qi) || (padm[tc*4+j] != 0.f);
                s = masked ? -1e30f : s;
                sv[i][j] = s;
                rmax = fmaxf(rmax, s);
            }
#pragma unroll
            for (int o = 8; o >= 1; o >>= 1)
                rmax = fmaxf(rmax, __shfl_xor_sync(0xffffffffu, rmax, o));
            const float mnew  = fmaxf(mrow[i], rmax);
            const float alpha = __expf(mrow[i] - mnew);
            float p[4];
            float rsum = 0.f;
#pragma unroll
            for (int j = 0; j < 4; j++) {
                const float pj = (sv[i][j] <= -1e30f) ? 0.f : __expf(sv[i][j] - mnew);
                p[j] = pj; rsum += pj;
            }
#pragma unroll
            for (int o = 8; o >= 1; o >>= 1)
                rsum += __shfl_xor_sync(0xffffffffu, rsum, o);
            lrow[i] = lrow[i] * alpha + rsum;
            mrow[i] = mnew;
#pragma unroll
            for (int j = 0; j < 4; j++) {
                acc[i][j] *= alpha;
                PsT[(tc*4+j)*64 + tr*4 + i] = p[j];
            }
        }
        __syncthreads();

#pragma unroll 4
        for (int c = 0; c < 64; c++) {
            float4 pa = *(const float4*)&PsT[c*64 + tr*4];
            float4 vb = *(const float4*)&Vs[c*64 + tc*4];
            float pv[4] = {pa.x, pa.y, pa.z, pa.w};
            float vv[4] = {vb.x, vb.y, vb.z, vb.w};
#pragma unroll
            for (int i = 0; i < 4; i++)
#pragma unroll
                for (int j = 0; j < 4; j++)
                    acc[i][j] = fmaf(pv[i], vv[j], acc[i][j]);
        }
    }

#pragma unroll
    for (int i = 0; i < 4; i++) {
        const float inv = (lrow[i] > 0.f) ? (1.f / lrow[i]) : 0.f;
        const int q = qi0 + tr*4 + i;
        float4 r = make_float4(acc[i][0]*inv, acc[i][1]*inv, acc[i][2]*inv, acc[i][3]*inv);
        *(float4*)&g_AO[((size_t)(b*SS + q)) * DM + h*DKH + tc*4] = r;
    }
}

// ---------------------------------------------------------------------------
extern "C" void kernel_launch(void* const* d_in, const int* in_sizes, int n_in,
                              void* d_out, int out_size)
{
    (void)in_sizes; (void)n_in; (void)out_size;
    const float* x   = (const float*)d_in[0];
    const int*   pad = (const int*)  d_in[1];
    const float* Wq  = (const float*)d_in[2];
    const float* bq  = (const float*)d_in[3];
    const float* Wk  = (const float*)d_in[4];
    const float* bk  = (const float*)d_in[5];
    const float* Wv  = (const float*)d_in[6];
    const float* bv  = (const float*)d_in[7];
    const float* Wo  = (const float*)d_in[8];
    const float* bo  = (const float*)d_in[9];
    float* out = (float*)d_out;

    float *Qp, *Kp, *Vp, *AOp;
    __nv_bfloat16 *xhi, *xlo, *whi, *wlo, *aohi, *aolo;
    cudaGetSymbolAddress((void**)&Qp,  g_Q);
    cudaGetSymbolAddress((void**)&Kp,  g_K);
    cudaGetSymbolAddress((void**)&Vp,  g_V);
    cudaGetSymbolAddress((void**)&AOp, g_AO);
    cudaGetSymbolAddress((void**)&xhi, g_xhi);
    cudaGetSymbolAddress((void**)&xlo, g_xlo);
    cudaGetSymbolAddress((void**)&whi, g_whi);
    cudaGetSymbolAddress((void**)&wlo, g_wlo);
    cudaGetSymbolAddress((void**)&aohi, g_aohi);
    cudaGetSymbolAddress((void**)&aolo, g_aolo);

    cudaFuncSetAttribute(flash_kernel,
                         cudaFuncAttributeMaxDynamicSharedMemorySize, 65536);
    cudaFuncSetAttribute(mma_gemm_kernel<1>,
                         cudaFuncAttributeMaxDynamicSharedMemorySize, GSMEM);
    cudaFuncSetAttribute(mma_gemm_kernel<0>,
                         cudaFuncAttributeMaxDynamicSharedMemorySize, GSMEM);

    const int NX4 = MROWS * DM / 4;   // 2097152
    const int NW4 = DM * DM / 4;      // 262144

    // 1) bf16 splits of x and weights
    split_kernel<<<(NX4 + 255) / 256, 256>>>(x, xhi, xlo, NX4);
    split_kernel<<<(NW4 + 255) / 256, 256>>>(Wq, whi + 0 * (size_t)DM*DM, wlo + 0 * (size_t)DM*DM, NW4);
    split_kernel<<<(NW4 + 255) / 256, 256>>>(Wk, whi + 1 * (size_t)DM*DM, wlo + 1 * (size_t)DM*DM, NW4);
    split_kernel<<<(NW4 + 255) / 256, 256>>>(Wv, whi + 2 * (size_t)DM*DM, wlo + 2 * (size_t)DM*DM, NW4);
    split_kernel<<<(NW4 + 255) / 256, 256>>>(Wo, whi + 3 * (size_t)DM*DM, wlo + 3 * (size_t)DM*DM, NW4);

    // 2) QKV projection (HMMA, 3-term split), scattered to [B,H,S,dk]
    mma_gemm_kernel<1><<<dim3(MROWS/128, DM/128, 3), 256, GSMEM>>>(
        xhi, xlo, whi, wlo, 0, bq, bk, bv, Qp, Kp, Vp);

    // 3) causal flash attention -> g_AO [B,S,D]
    flash_kernel<<<dim3(BB*NH, SS/64), 256, 65536>>>(pad);

    // 4) split AO, output projection -> d_out
    split_kernel<<<(NX4 + 255) / 256, 256>>>(AOp, aohi, aolo, NX4);
    mma_gemm_kernel<0><<<dim3(MROWS/128, DM/128, 1), 256, GSMEM>>>(
        aohi, aolo, whi, wlo, 3, bo, bo, bo, out, out, out);
}

// round 8
// speedup vs baseline: 1.4415x; 1.0428x over previous
#include <cuda_runtime.h>
#include <cuda_bf16.h>
#include <cstdint>

#define DM   1024
#define NH   16
#define DKH  64
#define BB   4
#define SS   2048
#define MROWS (BB*SS)   // 8192

using bf16 = __nv_bfloat16;

// ---------------- device scratch (allocation-free rule) ----------------
__device__ bf16 g_xhi[MROWS*DM];
__device__ bf16 g_xlo[MROWS*DM];
__device__ bf16 g_whi[4*DM*DM];
__device__ bf16 g_wlo[4*DM*DM];
__device__ bf16 g_qhi[BB*NH*SS*DKH];
__device__ bf16 g_qlo[BB*NH*SS*DKH];
__device__ bf16 g_khi[BB*NH*SS*DKH];
__device__ bf16 g_klo[BB*NH*SS*DKH];
__device__ bf16 g_vhi[BB*NH*SS*DKH];
__device__ bf16 g_vlo[BB*NH*SS*DKH];
__device__ bf16 g_aohi[MROWS*DM];
__device__ bf16 g_aolo[MROWS*DM];

// ---------------- PTX helpers (baseline ISA: sm_80-class) ----------------
__device__ __forceinline__ uint32_t smem_u32(const void* p) {
    uint32_t a;
    asm("{ .reg .u64 t; cvta.to.shared.u64 t, %1; cvt.u32.u64 %0, t; }" : "=r"(a) : "l"(p));
    return a;
}
__device__ __forceinline__ void cp16(uint32_t dst, const void* src) {
    asm volatile("cp.async.cg.shared.global [%0], [%1], 16;" :: "r"(dst), "l"(src));
}
__device__ __forceinline__ void cp_commit() {
    asm volatile("cp.async.commit_group;" ::: "memory");
}
template<int N> __device__ __forceinline__ void cp_wait() {
    asm volatile("cp.async.wait_group %0;" :: "n"(N) : "memory");
}
__device__ __forceinline__ void ldsm_x4(uint32_t& r0, uint32_t& r1, uint32_t& r2, uint32_t& r3,
                                        uint32_t addr) {
    asm volatile("ldmatrix.sync.aligned.m8n8.x4.shared.b16 {%0,%1,%2,%3}, [%4];"
                 : "=r"(r0), "=r"(r1), "=r"(r2), "=r"(r3) : "r"(addr));
}
__device__ __forceinline__ void ldsm_x4t(uint32_t& r0, uint32_t& r1, uint32_t& r2, uint32_t& r3,
                                         uint32_t addr) {
    asm volatile("ldmatrix.sync.aligned.m8n8.x4.trans.shared.b16 {%0,%1,%2,%3}, [%4];"
                 : "=r"(r0), "=r"(r1), "=r"(r2), "=r"(r3) : "r"(addr));
}
__device__ __forceinline__ void mma16816(float* c, const uint32_t* a, const uint32_t* b) {
    asm volatile(
        "mma.sync.aligned.m16n8k16.row.col.f32.bf16.bf16.f32 "
        "{%0,%1,%2,%3}, {%4,%5,%6,%7}, {%8,%9}, {%0,%1,%2,%3};"
        : "+f"(c[0]), "+f"(c[1]), "+f"(c[2]), "+f"(c[3])
        : "r"(a[0]), "r"(a[1]), "r"(a[2]), "r"(a[3]), "r"(b[0]), "r"(b[1]));
}
__device__ __forceinline__ uint32_t pack_bf2(float a, float b) {
    __nv_bfloat162 h = __floats2bfloat162_rn(a, b);
    return *(uint32_t*)&h;
}

// ---------------------------------------------------------------------------
// split: hi = bf16(x), lo = bf16(x - hi)   (4 elems/thread)
// ---------------------------------------------------------------------------
__global__ void split_kernel(const float* __restrict__ src,
                             bf16* __restrict__ hi, bf16* __restrict__ lo, int n4)
{
    int i = blockIdx.x * blockDim.x + threadIdx.x;
    if (i < n4) {
        float4 v = *(const float4*)(src + i * 4);
        bf16 h0 = __float2bfloat16(v.x);
        bf16 h1 = __float2bfloat16(v.y);
        bf16 h2 = __float2bfloat16(v.z);
        bf16 h3 = __float2bfloat16(v.w);
        __nv_bfloat162 H0{h0, h1}, H1{h2, h3};
        __nv_bfloat162 L0{__float2bfloat16(v.x - __bfloat162float(h0)),
                          __float2bfloat16(v.y - __bfloat162float(h1))};
        __nv_bfloat162 L1{__float2bfloat16(v.z - __bfloat162float(h2)),
                          __float2bfloat16(v.w - __bfloat162float(h3))};
        *(uint2*)(hi + i * 4) = make_uint2(*(uint32_t*)&H0, *(uint32_t*)&H1);
        *(uint2*)(lo + i * 4) = make_uint2(*(uint32_t*)&L0, *(uint32_t*)&L1);
    }
}

// ---------------------------------------------------------------------------
// HMMA GEMM: C[m,n] = sum_k A[m,k]*W[n,k] + bias[n]  (3-term bf16 split)
// SCATTER=1: write bf16 hi/lo into [B,H,S,dk] (QKV).  SCATTER=0: fp32 [M,DM].
// ---------------------------------------------------------------------------
#define BKG    32
#define NCHK   (DM / BKG)
#define ROWB   80
#define TILEB  (128 * ROWB)
#define STAGEB (4 * TILEB)
#define GSMEM  (2 * STAGEB)

template<int SCATTER>
__global__ void __launch_bounds__(256) mma_gemm_kernel(
    const bf16* __restrict__ Ahi, const bf16* __restrict__ Alo,
    const bf16* __restrict__ Whi, const bf16* __restrict__ Wlo, int wbase,
    const float* __restrict__ b0, const float* __restrict__ b1, const float* __restrict__ b2,
    float* __restrict__ Cfp,
    bf16* __restrict__ H0, bf16* __restrict__ L0,
    bf16* __restrict__ H1, bf16* __restrict__ L1,
    bf16* __restrict__ H2, bf16* __restrict__ L2)
{
    extern __shared__ char sm[];
    const uint32_t sbase = smem_u32(sm);

    const int tid  = threadIdx.x;
    const int warp = tid >> 5;
    const int lane = tid & 31;

    const int z  = blockIdx.z;
    const float* bias = (z == 0) ? b0 : (z == 1) ? b1 : b2;
    bf16* Hc = (z == 0) ? H0 : (z == 1) ? H1 : H2;
    bf16* Lc = (z == 0) ? L0 : (z == 1) ? L1 : L2;
    const int m0 = blockIdx.x * 128;
    const int n0 = blockIdx.y * 128;
    const int wsel = wbase + z;

    const int warp_m = (warp & 1) * 64;
    const int warp_n = (warp >> 1) * 32;

    const int ltile = tid >> 6;
    const int lrow  = tid & 63;
    const bf16* lsrc;
    {
        const size_t woff = (size_t)wsel * DM * DM;
        if      (ltile == 0) lsrc = Ahi + (size_t)(m0 + lrow) * DM;
        else if (ltile == 1) lsrc = Alo + (size_t)(m0 + lrow) * DM;
        else if (ltile == 2) lsrc = Whi + woff + (size_t)(n0 + lrow) * DM;
        else                 lsrc = Wlo + woff + (size_t)(n0 + lrow) * DM;
    }
    const uint32_t sdst0 = sbase + ltile * TILEB + lrow * ROWB;

    auto issue_stage = [&](int c, int s) {
        const int k0 = c * BKG;
        const uint32_t d0 = sdst0 + s * STAGEB;
        const char* p0 = (const char*)(lsrc + k0);
        const char* p1 = (const char*)(lsrc + 64 * DM + k0);
        cp16(d0 +  0, p0 +  0);
        cp16(d0 + 16, p0 + 16);
        cp16(d0 + 32, p0 + 32);
        cp16(d0 + 48, p0 + 48);
        cp16(d0 + 64 * ROWB +  0, p1 +  0);
        cp16(d0 + 64 * ROWB + 16, p1 + 16);
        cp16(d0 + 64 * ROWB + 32, p1 + 32);
        cp16(d0 + 64 * ROWB + 48, p1 + 48);
    };

    const uint32_t a_off = (uint32_t)(warp_m + (lane & 15)) * ROWB + ((lane >> 4) << 4);
    const uint32_t b_off = (uint32_t)(warp_n + ((lane & 16) >> 1) + (lane & 7)) * ROWB
                         + ((lane & 8) ? 16u : 0u);

    float acc[4][4][4];
#pragma unroll
    for (int i = 0; i < 4; i++)
#pragma unroll
        for (int j = 0; j < 4; j++)
#pragma unroll
            for (int r = 0; r < 4; r++) acc[i][j][r] = 0.f;

    issue_stage(0, 0);
    cp_commit();

    for (int c = 0; c < NCHK; c++) {
        const int s = c & 1;
        if (c + 1 < NCHK) { issue_stage(c + 1, 1 - s); cp_commit(); cp_wait<1>(); }
        else             { cp_wait<0>(); }
        __syncthreads();

        const uint32_t st   = sbase + s * STAGEB;
        const uint32_t tAhi = st + 0 * TILEB;
        const uint32_t tAlo = st + 1 * TILEB;
        const uint32_t tWhi = st + 2 * TILEB;
        const uint32_t tWlo = st + 3 * TILEB;

#pragma unroll
        for (int ks = 0; ks < 2; ks++) {
            const uint32_t ko = ks * 32;

            uint32_t bh[4][2], bl[4][2];
#pragma unroll
            for (int bj = 0; bj < 2; bj++) {
                uint32_t r0, r1, r2, r3;
                ldsm_x4(r0, r1, r2, r3, tWhi + b_off + bj * (16 * ROWB) + ko);
                bh[bj*2+0][0] = r0; bh[bj*2+0][1] = r1;
                bh[bj*2+1][0] = r2; bh[bj*2+1][1] = r3;
                ldsm_x4(r0, r1, r2, r3, tWlo + b_off + bj * (16 * ROWB) + ko);
                bl[bj*2+0][0] = r0; bl[bj*2+0][1] = r1;
                bl[bj*2+1][0] = r2; bl[bj*2+1][1] = r3;
            }

            uint32_t a[4][4];
#pragma unroll
            for (int mi = 0; mi < 4; mi++)
                ldsm_x4(a[mi][0], a[mi][1], a[mi][2], a[mi][3],
                        tAhi + a_off + mi * (16 * ROWB) + ko);
#pragma unroll
            for (int mi = 0; mi < 4; mi++)
#pragma unroll
                for (int nj = 0; nj < 4; nj++) {
                    mma16816(acc[mi][nj], a[mi], bh[nj]);
                    mma16816(acc[mi][nj], a[mi], bl[nj]);
                }
#pragma unroll
            for (int mi = 0; mi < 4; mi++)
                ldsm_x4(a[mi][0], a[mi][1], a[mi][2], a[mi][3],
                        tAlo + a_off + mi * (16 * ROWB) + ko);
#pragma unroll
            for (int mi = 0; mi < 4; mi++)
#pragma unroll
                for (int nj = 0; nj < 4; nj++)
                    mma16816(acc[mi][nj], a[mi], bh[nj]);
        }
        __syncthreads();
    }

    const int g = lane >> 2;
    const int t = lane & 3;
#pragma unroll
    for (int mi = 0; mi < 4; mi++) {
#pragma unroll
        for (int nj = 0; nj < 4; nj++) {
            const int n  = n0 + warp_n + nj * 8 + t * 2;
            const float bx = __ldg(bias + n);
            const float by = __ldg(bias + n + 1);
#pragma unroll
            for (int half = 0; half < 2; half++) {
                const int m = m0 + warp_m + mi * 16 + g + half * 8;
                float vx = acc[mi][nj][half * 2 + 0] + bx;
                float vy = acc[mi][nj][half * 2 + 1] + by;
                if (SCATTER) {
                    const int bidx = m >> 11;
                    const int sidx = m & 2047;
                    const int h    = n >> 6;
                    const int dc   = n & 63;
                    const size_t idx = ((size_t)((bidx * NH + h) * SS + sidx) << 6) + dc;
                    bf16 hx = __float2bfloat16(vx);
                    bf16 hy = __float2bfloat16(vy);
                    float lx = vx - __bfloat162float(hx);
                    float ly = vy - __bfloat162float(hy);
                    __nv_bfloat162 HH{hx, hy};
                    *(uint32_t*)&Hc[idx] = *(uint32_t*)&HH;
                    *(uint32_t*)&Lc[idx] = pack_bf2(lx, ly);
                } else {
                    *(float2*)&Cfp[(size_t)m * DM + n] = make_float2(vx, vy);
                }
            }
        }
    }
}

// ---------------------------------------------------------------------------
// HMMA flash attention (3-term split S and PV), causal + pad mask.
// CTA: 128 q rows of one (b,h); K/V chunks of 64; 8 warps x 16 rows.
// Writes aohi/aolo bf16 directly.
// ---------------------------------------------------------------------------
#define ROWAB  144               // 64 bf16 + 8 pad -> 144 bytes
#define TILEA  (64 * ROWAB)      // 9216
#define STAGEA (4 * TILEA + 256) // K hi/lo, V hi/lo + pad ints
#define ASMEM  (2 * STAGEA)      // 74240

__global__ void __launch_bounds__(256) mma_flash_kernel(const int* __restrict__ pad)
{
    extern __shared__ char sm[];
    const uint32_t sbase = smem_u32(sm);

    const int tid  = threadIdx.x;
    const int warp = tid >> 5;
    const int lane = tid & 31;
    const int g = lane >> 2;
    const int t = lane & 3;

    const int bh = blockIdx.x;               // 0..63
    const int qt = 15 - blockIdx.y;          // heavy tiles first
    const int b  = bh >> 4;
    const int h  = bh & 15;
    const int q0 = qt * 128;

    const size_t bhoff = (size_t)bh * SS * DKH;
    const bf16* Qhi = g_qhi + bhoff;
    const bf16* Qlo = g_qlo + bhoff;
    const bf16* Khi = g_khi + bhoff;
    const bf16* Klo = g_klo + bhoff;
    const bf16* Vhi = g_vhi + bhoff;
    const bf16* Vlo = g_vlo + bhoff;

    // ---- stage Q (hi in tiles 0-1, lo in tiles 2-3 of stage0) ----
    {
        const int sel = tid >> 7;            // 0 hi, 1 lo
        const int row = tid & 127;
        const bf16* src = (sel ? Qlo : Qhi) + (size_t)(q0 + row) * DKH;
        const uint32_t dst = sbase + sel * (2 * TILEA) + (row >> 6) * TILEA + (row & 63) * ROWAB;
#pragma unroll
        for (int i = 0; i < 8; i++) cp16(dst + i * 16, (const char*)src + i * 16);
    }
    cp_commit();
    cp_wait<0>();
    __syncthreads();

    // ---- Q frags into registers ----
    uint32_t qh[4][4], ql[4][4];
    {
        const int wrow = warp * 16 + (lane & 15);
        const uint32_t qb = sbase + (wrow >> 6) * TILEA + (wrow & 63) * ROWAB + ((lane >> 4) << 4);
#pragma unroll
        for (int kc = 0; kc < 4; kc++) {
            ldsm_x4(qh[kc][0], qh[kc][1], qh[kc][2], qh[kc][3], qb + kc * 32);
            ldsm_x4(ql[kc][0], ql[kc][1], ql[kc][2], ql[kc][3], qb + 2 * TILEA + kc * 32);
        }
    }
    __syncthreads();   // Q consumed; stage0 reusable

    float oacc[8][4];
#pragma unroll
    for (int j = 0; j < 8; j++)
#pragma unroll
        for (int r = 0; r < 4; r++) oacc[j][r] = 0.f;
    float mA = -1e30f, mB = -1e30f, lA = 0.f, lB = 0.f;

    const int cmax = 2 * qt + 1;
    const int qrA = q0 + warp * 16 + g;
    const int qrB = qrA + 8;

    auto issue = [&](int c) {
        const int stg = (c + 1) & 1;
        const int tile = tid >> 6;           // Khi,Klo,Vhi,Vlo
        const int row  = tid & 63;
        const bf16* src =
            (tile == 0) ? Khi + (size_t)(c * 64 + row) * DKH :
            (tile == 1) ? Klo + (size_t)(c * 64 + row) * DKH :
            (tile == 2) ? Vhi + (size_t)(c * 64 + row) * DKH :
                          Vlo + (size_t)(c * 64 + row) * DKH;
        const uint32_t dst = sbase + stg * STAGEA + tile * TILEA + row * ROWAB;
#pragma unroll
        for (int i = 0; i < 8; i++) cp16(dst + i * 16, (const char*)src + i * 16);
        if (tid < 16)
            cp16(sbase + stg * STAGEA + 4 * TILEA + tid * 16,
                 (const char*)(pad + b * SS + c * 64) + tid * 16);
    };

    issue(0); cp_commit();

    for (int c = 0; c <= cmax; c++) {
        if (c < cmax) { issue(c + 1); cp_commit(); cp_wait<1>(); }
        else          { cp_wait<0>(); }
        __syncthreads();

        const int stg = (c + 1) & 1;
        const uint32_t st = sbase + stg * STAGEA;
        const int* padsm = (const int*)(sm + (size_t)stg * STAGEA + 4 * TILEA);
        const int kc0 = c * 64;

        // ---- S = Q K^T (3-term) ----
        float sacc[8][4];
#pragma unroll
        for (int j = 0; j < 8; j++)
#pragma unroll
            for (int r = 0; r < 4; r++) sacc[j][r] = 0.f;

#pragma unroll
        for (int p = 0; p < 4; p++) {
            const uint32_t kb = st + (uint32_t)(p * 16 + ((lane & 16) >> 1) + (lane & 7)) * ROWAB
                              + ((lane & 8) ? 16u : 0u);
#pragma unroll
            for (int kc = 0; kc < 4; kc++) {
                uint32_t h0, h1, h2, h3, l0, l1, l2, l3;
                ldsm_x4(h0, h1, h2, h3, kb + kc * 32);
                ldsm_x4(l0, l1, l2, l3, kb + TILEA + kc * 32);
                uint32_t bhi0[2] = {h0, h1}, bhi1[2] = {h2, h3};
                uint32_t blo0[2] = {l0, l1}, blo1[2] = {l2, l3};
                mma16816(sacc[2*p+0], qh[kc], bhi0);
                mma16816(sacc[2*p+1], qh[kc], bhi1);
                mma16816(sacc[2*p+0], qh[kc], blo0);
                mma16816(sacc[2*p+1], qh[kc], blo1);
                mma16816(sacc[2*p+0], ql[kc], bhi0);
                mma16816(sacc[2*p+1], ql[kc], bhi1);
            }
        }

        // ---- masked online softmax ----
        float rmA = -1e30f, rmB = -1e30f;
#pragma unroll
        for (int j = 0; j < 8; j++) {
            const int k0i = kc0 + j * 8 + t * 2;
            const bool pm0 = padsm[j * 8 + t * 2]     != 0;
            const bool pm1 = padsm[j * 8 + t * 2 + 1] != 0;
            float s0 = sacc[j][0] * 0.125f; if (k0i     > qrA || pm0) s0 = -1e30f;
            float s1 = sacc[j][1] * 0.125f; if (k0i + 1 > qrA || pm1) s1 = -1e30f;
            float s2 = sacc[j][2] * 0.125f; if (k0i     > qrB || pm0) s2 = -1e30f;
            float s3 = sacc[j][3] * 0.125f; if (k0i + 1 > qrB || pm1) s3 = -1e30f;
            sacc[j][0] = s0; sacc[j][1] = s1; sacc[j][2] = s2; sacc[j][3] = s3;
            rmA = fmaxf(rmA, fmaxf(s0, s1));
            rmB = fmaxf(rmB, fmaxf(s2, s3));
        }
#pragma unroll
        for (int o = 1; o <= 2; o <<= 1) {
            rmA = fmaxf(rmA, __shfl_xor_sync(0xffffffffu, rmA, o));
            rmB = fmaxf(rmB, __shfl_xor_sync(0xffffffffu, rmB, o));
        }
        const float mnA = fmaxf(mA, rmA);
        const float mnB = fmaxf(mB, rmB);
        const float aAl = __expf(mA - mnA);
        const float aBl = __expf(mB - mnB);
        mA = mnA; mB = mnB;

        float sumA = 0.f, sumB = 0.f;
#pragma unroll
        for (int j = 0; j < 8; j++) {
            float p0 = (sacc[j][0] <= -1e30f) ? 0.f : __expf(sacc[j][0] - mnA);
            float p1 = (sacc[j][1] <= -1e30f) ? 0.f : __expf(sacc[j][1] - mnA);
            float p2 = (sacc[j][2] <= -1e30f) ? 0.f : __expf(sacc[j][2] - mnB);
            float p3 = (sacc[j][3] <= -1e30f) ? 0.f : __expf(sacc[j][3] - mnB);
            sumA += p0 + p1; sumB += p2 + p3;
            sacc[j][0] = p0; sacc[j][1] = p1; sacc[j][2] = p2; sacc[j][3] = p3;
        }
#pragma unroll
        for (int o = 1; o <= 2; o <<= 1) {
            sumA += __shfl_xor_sync(0xffffffffu, sumA, o);
            sumB += __shfl_xor_sync(0xffffffffu, sumB, o);
        }
        lA = lA * aAl + sumA;
        lB = lB * aBl + sumB;
#pragma unroll
        for (int j = 0; j < 8; j++) {
            oacc[j][0] *= aAl; oacc[j][1] *= aAl;
            oacc[j][2] *= aBl; oacc[j][3] *= aBl;
        }

        // ---- P -> bf16 hi/lo A-frags (register reuse, no smem) ----
        uint32_t pah[4][4], pal[4][4];
#pragma unroll
        for (int kc = 0; kc < 4; kc++) {
            const int j0 = 2 * kc, j1 = 2 * kc + 1;
            float ph[8], pl[8];
            const float pv[8] = { sacc[j0][0], sacc[j0][1], sacc[j0][2], sacc[j0][3],
                                  sacc[j1][0], sacc[j1][1], sacc[j1][2], sacc[j1][3] };
#pragma unroll
            for (int e = 0; e < 8; e++) {
                bf16 hh = __float2bfloat16(pv[e]);
                ph[e] = __bfloat162float(hh);
                pl[e] = pv[e] - ph[e];
            }
            pah[kc][0] = pack_bf2(ph[0], ph[1]);
            pah[kc][1] = pack_bf2(ph[2], ph[3]);
            pah[kc][2] = pack_bf2(ph[4], ph[5]);
            pah[kc][3] = pack_bf2(ph[6], ph[7]);
            pal[kc][0] = pack_bf2(pl[0], pl[1]);
            pal[kc][1] = pack_bf2(pl[2], pl[3]);
            pal[kc][2] = pack_bf2(pl[4], pl[5]);
            pal[kc][3] = pack_bf2(pl[6], pl[7]);
        }

        // ---- O += P V (3-term), V via ldmatrix.trans ----
#pragma unroll
        for (int p = 0; p < 4; p++) {
#pragma unroll
            for (int kc = 0; kc < 4; kc++) {
                const uint32_t vb = st + 2 * TILEA
                                  + (uint32_t)(kc * 16 + (lane & 15)) * ROWAB
                                  + (uint32_t)(p * 32) + ((lane >> 4) << 4);
                uint32_t h0, h1, h2, h3, l0, l1, l2, l3;
                ldsm_x4t(h0, h1, h2, h3, vb);
                ldsm_x4t(l0, l1, l2, l3, vb + TILEA);
                uint32_t vhi0[2] = {h0, h1}, vhi1[2] = {h2, h3};
                uint32_t vlo0[2] = {l0, l1}, vlo1[2] = {l2, l3};
                mma16816(oacc[2*p+0], pah[kc], vhi0);
                mma16816(oacc[2*p+1], pah[kc], vhi1);
                mma16816(oacc[2*p+0], pah[kc], vlo0);
                mma16816(oacc[2*p+1], pah[kc], vlo1);
                mma16816(oacc[2*p+0], pal[kc], vhi0);
                mma16816(oacc[2*p+1], pal[kc], vhi1);
            }
        }
        __syncthreads();   // protect stage from next issue
    }

    // ---- epilogue: normalize, split to bf16 hi/lo, write [B,S,DM] ----
    const float invA = (lA > 0.f) ? (1.f / lA) : 0.f;
    const float invB = (lB > 0.f) ? (1.f / lB) : 0.f;
    const size_t rowA = (size_t)(b * SS + qrA) * DM + h * 64;
    const size_t rowB = (size_t)(b * SS + qrB) * DM + h * 64;
#pragma unroll
    for (int j = 0; j < 8; j++) {
        const int n = j * 8 + t * 2;
        float x0 = oacc[j][0] * invA, x1 = oacc[j][1] * invA;
        float y0 = oacc[j][2] * invB, y1 = oacc[j][3] * invB;
        bf16 hx0 = __float2bfloat16(x0), hx1 = __float2bfloat16(x1);
        bf16 hy0 = __float2bfloat16(y0), hy1 = __float2bfloat16(y1);
        __nv_bfloat162 HA{hx0, hx1}, HB{hy0, hy1};
        *(uint32_t*)&g_aohi[rowA + n] = *(uint32_t*)&HA;
        *(uint32_t*)&g_aohi[rowB + n] = *(uint32_t*)&HB;
        *(uint32_t*)&g_aolo[rowA + n] =
            pack_bf2(x0 - __bfloat162float(hx0), x1 - __bfloat162float(hx1));
        *(uint32_t*)&g_aolo[rowB + n] =
            pack_bf2(y0 - __bfloat162float(hy0), y1 - __bfloat162float(hy1));
    }
}

// ---------------------------------------------------------------------------
extern "C" void kernel_launch(void* const* d_in, const int* in_sizes, int n_in,
                              void* d_out, int out_size)
{
    (void)in_sizes; (void)n_in; (void)out_size;
    const float* x   = (const float*)d_in[0];
    const int*   pad = (const int*)  d_in[1];
    const float* Wq  = (const float*)d_in[2];
    const float* bq  = (const float*)d_in[3];
    const float* Wk  = (const float*)d_in[4];
    const float* bk  = (const float*)d_in[5];
    const float* Wv  = (const float*)d_in[6];
    const float* bv  = (const float*)d_in[7];
    const float* Wo  = (const float*)d_in[8];
    const float* bo  = (const float*)d_in[9];
    float* out = (float*)d_out;

    bf16 *xhi, *xlo, *whi, *wlo, *aohi, *aolo;
    bf16 *qhi, *qlo, *khi, *klo, *vhi, *vlo;
    cudaGetSymbolAddress((void**)&xhi, g_xhi);
    cudaGetSymbolAddress((void**)&xlo, g_xlo);
    cudaGetSymbolAddress((void**)&whi, g_whi);
    cudaGetSymbolAddress((void**)&wlo, g_wlo);
    cudaGetSymbolAddress((void**)&aohi, g_aohi);
    cudaGetSymbolAddress((void**)&aolo, g_aolo);
    cudaGetSymbolAddress((void**)&qhi, g_qhi);
    cudaGetSymbolAddress((void**)&qlo, g_qlo);
    cudaGetSymbolAddress((void**)&khi, g_khi);
    cudaGetSymbolAddress((void**)&klo, g_klo);
    cudaGetSymbolAddress((void**)&vhi, g_vhi);
    cudaGetSymbolAddress((void**)&vlo, g_vlo);

    cudaFuncSetAttribute(mma_gemm_kernel<1>,
                         cudaFuncAttributeMaxDynamicSharedMemorySize, GSMEM);
    cudaFuncSetAttribute(mma_gemm_kernel<0>,
                         cudaFuncAttributeMaxDynamicSharedMemorySize, GSMEM);
    cudaFuncSetAttribute(mma_flash_kernel,
                         cudaFuncAttributeMaxDynamicSharedMemorySize, ASMEM);

    const int NX4 = MROWS * DM / 4;
    const int NW4 = DM * DM / 4;

    // 1) bf16 splits of x and weights
    split_kernel<<<(NX4 + 255) / 256, 256>>>(x, xhi, xlo, NX4);
    split_kernel<<<(NW4 + 255) / 256, 256>>>(Wq, whi + 0 * (size_t)DM*DM, wlo + 0 * (size_t)DM*DM, NW4);
    split_kernel<<<(NW4 + 255) / 256, 256>>>(Wk, whi + 1 * (size_t)DM*DM, wlo + 1 * (size_t)DM*DM, NW4);
    split_kernel<<<(NW4 + 255) / 256, 256>>>(Wv, whi + 2 * (size_t)DM*DM, wlo + 2 * (size_t)DM*DM, NW4);
    split_kernel<<<(NW4 + 255) / 256, 256>>>(Wo, whi + 3 * (size_t)DM*DM, wlo + 3 * (size_t)DM*DM, NW4);

    // 2) QKV projection -> bf16 hi/lo [B,H,S,dk]
    mma_gemm_kernel<1><<<dim3(MROWS/128, DM/128, 3), 256, GSMEM>>>(
        xhi, xlo, whi, wlo, 0, bq, bk, bv, nullptr,
        qhi, qlo, khi, klo, vhi, vlo);

    // 3) HMMA flash attention -> aohi/aolo [B,S,DM]
    mma_flash_kernel<<<dim3(BB*NH, SS/128), 256, ASMEM>>>(pad);

    // 4) output projection -> d_out (fp32)
    mma_gemm_kernel<0><<<dim3(MROWS/128, DM/128, 1), 256, GSMEM>>>(
        aohi, aolo, whi, wlo, 3, bo, bo, bo, out,
        nullptr, nullptr, nullptr, nullptr, nullptr, nullptr);
}

// round 9
// speedup vs baseline: 2.9601x; 2.0535x over previous
#include <cuda_runtime.h>
#include <cuda_fp16.h>
#include <cstdint>

#define DM   1024
#define NH   16
#define DKH  64
#define BB   4
#define SS   2048
#define MROWS (BB*SS)   // 8192

// ---------------- device scratch (allocation-free rule) ----------------
__device__ __half g_xhi[MROWS*DM];
__device__ __half g_xlo[MROWS*DM];
__device__ __half g_w[4*DM*DM];          // quantized weights (single fp16)
__device__ __half g_qhi[BB*NH*SS*DKH];
__device__ __half g_qlo[BB*NH*SS*DKH];
__device__ __half g_k[BB*NH*SS*DKH];     // single fp16
__device__ __half g_v[BB*NH*SS*DKH];     // single fp16
__device__ __half g_aohi[MROWS*DM];
__device__ __half g_aolo[MROWS*DM];

// ---------------- PTX helpers (baseline ISA: sm_80-class) ----------------
__device__ __forceinline__ uint32_t smem_u32(const void* p) {
    uint32_t a;
    asm("{ .reg .u64 t; cvta.to.shared.u64 t, %1; cvt.u32.u64 %0, t; }" : "=r"(a) : "l"(p));
    return a;
}
__device__ __forceinline__ void cp16(uint32_t dst, const void* src) {
    asm volatile("cp.async.cg.shared.global [%0], [%1], 16;" :: "r"(dst), "l"(src));
}
__device__ __forceinline__ void cp_commit() {
    asm volatile("cp.async.commit_group;" ::: "memory");
}
template<int N> __device__ __forceinline__ void cp_wait() {
    asm volatile("cp.async.wait_group %0;" :: "n"(N) : "memory");
}
__device__ __forceinline__ void ldsm_x4(uint32_t& r0, uint32_t& r1, uint32_t& r2, uint32_t& r3,
                                        uint32_t addr) {
    asm volatile("ldmatrix.sync.aligned.m8n8.x4.shared.b16 {%0,%1,%2,%3}, [%4];"
                 : "=r"(r0), "=r"(r1), "=r"(r2), "=r"(r3) : "r"(addr));
}
__device__ __forceinline__ void ldsm_x4t(uint32_t& r0, uint32_t& r1, uint32_t& r2, uint32_t& r3,
                                         uint32_t addr) {
    asm volatile("ldmatrix.sync.aligned.m8n8.x4.trans.shared.b16 {%0,%1,%2,%3}, [%4];"
                 : "=r"(r0), "=r"(r1), "=r"(r2), "=r"(r3) : "r"(addr));
}
__device__ __forceinline__ void mma16816h(float* c, const uint32_t* a, const uint32_t* b) {
    asm volatile(
        "mma.sync.aligned.m16n8k16.row.col.f32.f16.f16.f32 "
        "{%0,%1,%2,%3}, {%4,%5,%6,%7}, {%8,%9}, {%0,%1,%2,%3};"
        : "+f"(c[0]), "+f"(c[1]), "+f"(c[2]), "+f"(c[3])
        : "r"(a[0]), "r"(a[1]), "r"(a[2]), "r"(a[3]), "r"(b[0]), "r"(b[1]));
}
__device__ __forceinline__ uint32_t packh2(float a, float b) {
    __half2 h = __floats2half2_rn(a, b);
    return *(uint32_t*)&h;
}

// ---------------------------------------------------------------------------
// split: hi = fp16(x), lo = fp16(x - hi)   (4 elems/thread)
// ---------------------------------------------------------------------------
__global__ void split_kernel(const float* __restrict__ src,
                             __half* __restrict__ hi, __half* __restrict__ lo, int n4)
{
    int i = blockIdx.x * blockDim.x + threadIdx.x;
    if (i < n4) {
        float4 v = *(const float4*)(src + i * 4);
        __half h0 = __float2half(v.x), h1 = __float2half(v.y);
        __half h2 = __float2half(v.z), h3 = __float2half(v.w);
        *(uint2*)(hi + i * 4) = make_uint2(packh2(__half2float(h0), 0.f) | (packh2(__half2float(h1), 0.f) << 16),
                                           packh2(__half2float(h2), 0.f) | (packh2(__half2float(h3), 0.f) << 16));
        // simpler: repack directly
        __half2 H0{h0, h1}, H1{h2, h3};
        *(uint2*)(hi + i * 4) = make_uint2(*(uint32_t*)&H0, *(uint32_t*)&H1);
        __half2 L0 = __floats2half2_rn(v.x - __half2float(h0), v.y - __half2float(h1));
        __half2 L1 = __floats2half2_rn(v.z - __half2float(h2), v.w - __half2float(h3));
        *(uint2*)(lo + i * 4) = make_uint2(*(uint32_t*)&L0, *(uint32_t*)&L1);
    }
}

// quantize 4 weight matrices to fp16 (grid.y selects matrix)
__global__ void quant_kernel(const float* __restrict__ s0, const float* __restrict__ s1,
                             const float* __restrict__ s2, const float* __restrict__ s3,
                             __half* __restrict__ dst, int n4)
{
    int i = blockIdx.x * blockDim.x + threadIdx.x;
    const int w = blockIdx.y;
    if (i < n4) {
        const float* src = (w == 0) ? s0 : (w == 1) ? s1 : (w == 2) ? s2 : s3;
        float4 v = *(const float4*)(src + i * 4);
        __half2 H0 = __floats2half2_rn(v.x, v.y);
        __half2 H1 = __floats2half2_rn(v.z, v.w);
        *(uint2*)(dst + (size_t)w * DM * DM + i * 4) =
            make_uint2(*(uint32_t*)&H0, *(uint32_t*)&H1);
    }
}

// ---------------------------------------------------------------------------
// HMMA GEMM (fp16, 2-term): C[m,n] = (Ahi+Alo)[m,:]*W[n,:] + bias[n]
// CTA 128x128, BK=32, 256 threads (8 warps 2m x 4n), cp.async double buffer.
// SCATTER=1: scatter into [B,H,S,dk]; z=0 writes hi+lo (Q), z=1,2 hi only (K,V).
// SCATTER=0: fp32 row-major [M,DM].
// ---------------------------------------------------------------------------
#define BKG    32
#define NCHK   (DM / BKG)         // 32
#define ROWB   80                 // 32 fp16 (64B) + 16B pad
#define TILEB  (128 * ROWB)       // 10240
#define STAGEB (3 * TILEB)        // Ahi, Alo, W
#define GSMEM  (2 * STAGEB)       // 61440

template<int SCATTER>
__global__ void __launch_bounds__(256) mma_gemm_kernel(
    const __half* __restrict__ Ahi, const __half* __restrict__ Alo,
    const __half* __restrict__ W, int wbase,
    const float* __restrict__ b0, const float* __restrict__ b1, const float* __restrict__ b2,
    float* __restrict__ Cfp,
    __half* __restrict__ H0, __half* __restrict__ L0,
    __half* __restrict__ H1, __half* __restrict__ H2)
{
    extern __shared__ char sm[];
    const uint32_t sbase = smem_u32(sm);

    const int tid  = threadIdx.x;
    const int warp = tid >> 5;
    const int lane = tid & 31;

    const int z  = blockIdx.z;
    const float* bias = (z == 0) ? b0 : (z == 1) ? b1 : b2;
    __half* Hc = (z == 0) ? H0 : (z == 1) ? H1 : H2;
    const bool wantLo = SCATTER && (z == 0);
    const int m0 = blockIdx.x * 128;
    const int n0 = blockIdx.y * 128;

    const int warp_m = (warp & 1) * 64;
    const int warp_n = (warp >> 1) * 32;

    // loaders: jobs 0..255 -> tiles 0,1 (Ahi,Alo); tid<128 also loads W tile
    const int arow = tid & 127;
    const __half* asrc = ((tid >> 7) ? Alo : Ahi) + (size_t)(m0 + arow) * DM;
    const uint32_t adst0 = sbase + (tid >> 7) * TILEB + arow * ROWB;
    const __half* wsrc = W + (size_t)(wbase + z) * DM * DM + (size_t)(n0 + tid) * DM; // valid tid<128
    const uint32_t wdst0 = sbase + 2 * TILEB + tid * ROWB;

    auto issue_stage = [&](int c, int s) {
        const int k0 = c * BKG;
        const uint32_t da = adst0 + s * STAGEB;
        const char* pa = (const char*)(asrc + k0);
        cp16(da +  0, pa +  0);
        cp16(da + 16, pa + 16);
        cp16(da + 32, pa + 32);
        cp16(da + 48, pa + 48);
        if (tid < 128) {
            const uint32_t dw = wdst0 + s * STAGEB;
            const char* pw = (const char*)(wsrc + k0);
            cp16(dw +  0, pw +  0);
            cp16(dw + 16, pw + 16);
            cp16(dw + 32, pw + 32);
            cp16(dw + 48, pw + 48);
        }
    };

    const uint32_t a_off = (uint32_t)(warp_m + (lane & 15)) * ROWB + ((lane >> 4) << 4);
    const uint32_t b_off = (uint32_t)(warp_n + ((lane & 16) >> 1) + (lane & 7)) * ROWB
                         + ((lane & 8) ? 16u : 0u);

    float acc[4][4][4];
#pragma unroll
    for (int i = 0; i < 4; i++)
#pragma unroll
        for (int j = 0; j < 4; j++)
#pragma unroll
            for (int r = 0; r < 4; r++) acc[i][j][r] = 0.f;

    issue_stage(0, 0);
    cp_commit();

    for (int c = 0; c < NCHK; c++) {
        const int s = c & 1;
        if (c + 1 < NCHK) { issue_stage(c + 1, 1 - s); cp_commit(); cp_wait<1>(); }
        else             { cp_wait<0>(); }
        __syncthreads();

        const uint32_t st   = sbase + s * STAGEB;
        const uint32_t tAhi = st + 0 * TILEB;
        const uint32_t tAlo = st + 1 * TILEB;
        const uint32_t tW   = st + 2 * TILEB;

#pragma unroll
        for (int ks = 0; ks < 2; ks++) {
            const uint32_t ko = ks * 32;

            uint32_t bw[4][2];
#pragma unroll
            for (int bj = 0; bj < 2; bj++) {
                uint32_t r0, r1, r2, r3;
                ldsm_x4(r0, r1, r2, r3, tW + b_off + bj * (16 * ROWB) + ko);
                bw[bj*2+0][0] = r0; bw[bj*2+0][1] = r1;
                bw[bj*2+1][0] = r2; bw[bj*2+1][1] = r3;
            }

            uint32_t a[4][4];
#pragma unroll
            for (int mi = 0; mi < 4; mi++)
                ldsm_x4(a[mi][0], a[mi][1], a[mi][2], a[mi][3],
                        tAhi + a_off + mi * (16 * ROWB) + ko);
#pragma unroll
            for (int mi = 0; mi < 4; mi++)
#pragma unroll
                for (int nj = 0; nj < 4; nj++)
                    mma16816h(acc[mi][nj], a[mi], bw[nj]);
#pragma unroll
            for (int mi = 0; mi < 4; mi++)
                ldsm_x4(a[mi][0], a[mi][1], a[mi][2], a[mi][3],
                        tAlo + a_off + mi * (16 * ROWB) + ko);
#pragma unroll
            for (int mi = 0; mi < 4; mi++)
#pragma unroll
                for (int nj = 0; nj < 4; nj++)
                    mma16816h(acc[mi][nj], a[mi], bw[nj]);
        }
        __syncthreads();
    }

    const int g = lane >> 2;
    const int t = lane & 3;
#pragma unroll
    for (int mi = 0; mi < 4; mi++) {
#pragma unroll
        for (int nj = 0; nj < 4; nj++) {
            const int n  = n0 + warp_n + nj * 8 + t * 2;
            const float bx = __ldg(bias + n);
            const float by = __ldg(bias + n + 1);
#pragma unroll
            for (int half = 0; half < 2; half++) {
                const int m = m0 + warp_m + mi * 16 + g + half * 8;
                float vx = acc[mi][nj][half * 2 + 0] + bx;
                float vy = acc[mi][nj][half * 2 + 1] + by;
                if (SCATTER) {
                    const int bidx = m >> 11;
                    const int sidx = m & 2047;
                    const int hh   = n >> 6;
                    const int dc   = n & 63;
                    const size_t idx = ((size_t)((bidx * NH + hh) * SS + sidx) << 6) + dc;
                    __half hx = __float2half(vx);
                    __half hy = __float2half(vy);
                    __half2 HH{hx, hy};
                    *(uint32_t*)&Hc[idx] = *(uint32_t*)&HH;
                    if (wantLo)
                        *(uint32_t*)&L0[idx] =
                            packh2(vx - __half2float(hx), vy - __half2float(hy));
                } else {
                    *(float2*)&Cfp[(size_t)m * DM + n] = make_float2(vx, vy);
                }
            }
        }
    }
}

// ---------------------------------------------------------------------------
// HMMA flash attention (fp16: Q 2-term, K/V single), causal + pad mask.
// CTA: 128 q rows of one (b,h); K/V chunks of 64; 8 warps x 16 rows.
// Writes aohi/aolo fp16 directly.
// ---------------------------------------------------------------------------
#define ROWAB  144               // 64 fp16 (128B) + 16 pad
#define TILEA  (64 * ROWAB)      // 9216
#define STAGEA (2 * TILEA + 256) // K, V + pad ints
#define ASMEM  (2 * STAGEA)      // 37376

__global__ void __launch_bounds__(256) mma_flash_kernel(const int* __restrict__ pad)
{
    extern __shared__ char sm[];
    const uint32_t sbase = smem_u32(sm);

    const int tid  = threadIdx.x;
    const int warp = tid >> 5;
    const int lane = tid & 31;
    const int g = lane >> 2;
    const int t = lane & 3;

    const int bh = blockIdx.x;               // 0..63
    const int qt = 15 - blockIdx.y;          // heavy tiles first
    const int b  = bh >> 4;
    const int h  = bh & 15;
    const int q0 = qt * 128;

    const size_t bhoff = (size_t)bh * SS * DKH;
    const __half* Qhi = g_qhi + bhoff;
    const __half* Qlo = g_qlo + bhoff;
    const __half* Kq  = g_k   + bhoff;
    const __half* Vq  = g_v   + bhoff;

    // ---- stage Q (hi tiles 0-1, lo tiles 2-3) ----
    {
        const int sel = tid >> 7;            // 0 hi, 1 lo
        const int row = tid & 127;
        const __half* src = (sel ? Qlo : Qhi) + (size_t)(q0 + row) * DKH;
        const uint32_t dst = sbase + sel * (2 * TILEA) + (row >> 6) * TILEA + (row & 63) * ROWAB;
#pragma unroll
        for (int i = 0; i < 8; i++) cp16(dst + i * 16, (const char*)src + i * 16);
    }
    cp_commit();
    cp_wait<0>();
    __syncthreads();

    // ---- Q frags into registers ----
    uint32_t qh[4][4], ql[4][4];
    {
        const int wrow = warp * 16 + (lane & 15);
        const uint32_t qb = sbase + (wrow >> 6) * TILEA + (wrow & 63) * ROWAB + ((lane >> 4) << 4);
#pragma unroll
        for (int kc = 0; kc < 4; kc++) {
            ldsm_x4(qh[kc][0], qh[kc][1], qh[kc][2], qh[kc][3], qb + kc * 32);
            ldsm_x4(ql[kc][0], ql[kc][1], ql[kc][2], ql[kc][3], qb + 2 * TILEA + kc * 32);
        }
    }
    __syncthreads();   // Q consumed; smem reusable

    float oacc[8][4];
#pragma unroll
    for (int j = 0; j < 8; j++)
#pragma unroll
        for (int r = 0; r < 4; r++) oacc[j][r] = 0.f;
    float mA = -1e30f, mB = -1e30f, lA = 0.f, lB = 0.f;

    const int cmax = 2 * qt + 1;
    const int qrA = q0 + warp * 16 + g;
    const int qrB = qrA + 8;

    auto issue = [&](int c) {
        const int stg = (c + 1) & 1;
        const int tile = tid >> 7;           // 0:K, 1:V
        const int rjob = tid & 127;
        const int row  = rjob >> 1;
        const int hlf  = rjob & 1;
        const __half* src = (tile ? Vq : Kq) + (size_t)(c * 64 + row) * DKH + hlf * 32;
        const uint32_t dst = sbase + stg * STAGEA + tile * TILEA + row * ROWAB + hlf * 64;
#pragma unroll
        for (int i = 0; i < 4; i++) cp16(dst + i * 16, (const char*)src + i * 16);
        if (tid < 16)
            cp16(sbase + stg * STAGEA + 2 * TILEA + tid * 16,
                 (const char*)(pad + b * SS + c * 64) + tid * 16);
    };

    issue(0); cp_commit();

    for (int c = 0; c <= cmax; c++) {
        if (c < cmax) { issue(c + 1); cp_commit(); cp_wait<1>(); }
        else          { cp_wait<0>(); }
        __syncthreads();

        const int stg = (c + 1) & 1;
        const uint32_t st = sbase + stg * STAGEA;
        const int* padsm = (const int*)(sm + (size_t)stg * STAGEA + 2 * TILEA);
        const int kc0 = c * 64;

        // ---- S = Q K^T (2-term) ----
        float sacc[8][4];
#pragma unroll
        for (int j = 0; j < 8; j++)
#pragma unroll
            for (int r = 0; r < 4; r++) sacc[j][r] = 0.f;

#pragma unroll
        for (int p = 0; p < 4; p++) {
            const uint32_t kb = st + (uint32_t)(p * 16 + ((lane & 16) >> 1) + (lane & 7)) * ROWAB
                              + ((lane & 8) ? 16u : 0u);
#pragma unroll
            for (int kc = 0; kc < 4; kc++) {
                uint32_t k0, k1, k2, k3;
                ldsm_x4(k0, k1, k2, k3, kb + kc * 32);
                uint32_t bk0[2] = {k0, k1}, bk1[2] = {k2, k3};
                mma16816h(sacc[2*p+0], qh[kc], bk0);
                mma16816h(sacc[2*p+1], qh[kc], bk1);
                mma16816h(sacc[2*p+0], ql[kc], bk0);
                mma16816h(sacc[2*p+1], ql[kc], bk1);
            }
        }

        // ---- masked online softmax ----
        float rmA = -1e30f, rmB = -1e30f;
#pragma unroll
        for (int j = 0; j < 8; j++) {
            const int k0i = kc0 + j * 8 + t * 2;
            const bool pm0 = padsm[j * 8 + t * 2]     != 0;
            const bool pm1 = padsm[j * 8 + t * 2 + 1] != 0;
            float s0 = sacc[j][0] * 0.125f; if (k0i     > qrA || pm0) s0 = -1e30f;
            float s1 = sacc[j][1] * 0.125f; if (k0i + 1 > qrA || pm1) s1 = -1e30f;
            float s2 = sacc[j][2] * 0.125f; if (k0i     > qrB || pm0) s2 = -1e30f;
            float s3 = sacc[j][3] * 0.125f; if (k0i + 1 > qrB || pm1) s3 = -1e30f;
            sacc[j][0] = s0; sacc[j][1] = s1; sacc[j][2] = s2; sacc[j][3] = s3;
            rmA = fmaxf(rmA, fmaxf(s0, s1));
            rmB = fmaxf(rmB, fmaxf(s2, s3));
        }
#pragma unroll
        for (int o = 1; o <= 2; o <<= 1) {
            rmA = fmaxf(rmA, __shfl_xor_sync(0xffffffffu, rmA, o));
            rmB = fmaxf(rmB, __shfl_xor_sync(0xffffffffu, rmB, o));
        }
        const float mnA = fmaxf(mA, rmA);
        const float mnB = fmaxf(mB, rmB);
        const float aAl = __expf(mA - mnA);
        const float aBl = __expf(mB - mnB);
        mA = mnA; mB = mnB;

        float sumA = 0.f, sumB = 0.f;
#pragma unroll
        for (int j = 0; j < 8; j++) {
            float p0 = (sacc[j][0] <= -1e30f) ? 0.f : __expf(sacc[j][0] - mnA);
            float p1 = (sacc[j][1] <= -1e30f) ? 0.f : __expf(sacc[j][1] - mnA);
            float p2 = (sacc[j][2] <= -1e30f) ? 0.f : __expf(sacc[j][2] - mnB);
            float p3 = (sacc[j][3] <= -1e30f) ? 0.f : __expf(sacc[j][3] - mnB);
            sumA += p0 + p1; sumB += p2 + p3;
            sacc[j][0] = p0; sacc[j][1] = p1; sacc[j][2] = p2; sacc[j][3] = p3;
        }
#pragma unroll
        for (int o = 1; o <= 2; o <<= 1) {
            sumA += __shfl_xor_sync(0xffffffffu, sumA, o);
            sumB += __shfl_xor_sync(0xffffffffu, sumB, o);
        }
        lA = lA * aAl + sumA;
        lB = lB * aBl + sumB;
#pragma unroll
        for (int j = 0; j < 8; j++) {
            oacc[j][0] *= aAl; oacc[j][1] *= aAl;
            oacc[j][2] *= aBl; oacc[j][3] *= aBl;
        }

        // ---- P -> fp16 hi/lo A-frags (register reuse, no smem) ----
        uint32_t pah[4][4], pal[4][4];
#pragma unroll
        for (int kc = 0; kc < 4; kc++) {
            const int j0 = 2 * kc, j1 = 2 * kc + 1;
            float ph[8], pl[8];
            const float pv[8] = { sacc[j0][0], sacc[j0][1], sacc[j0][2], sacc[j0][3],
                                  sacc[j1][0], sacc[j1][1], sacc[j1][2], sacc[j1][3] };
#pragma unroll
            for (int e = 0; e < 8; e++) {
                __half hh = __float2half(pv[e]);
                ph[e] = __half2float(hh);
                pl[e] = pv[e] - ph[e];
            }
            pah[kc][0] = packh2(ph[0], ph[1]);
            pah[kc][1] = packh2(ph[2], ph[3]);
            pah[kc][2] = packh2(ph[4], ph[5]);
            pah[kc][3] = packh2(ph[6], ph[7]);
            pal[kc][0] = packh2(pl[0], pl[1]);
            pal[kc][1] = packh2(pl[2], pl[3]);
            pal[kc][2] = packh2(pl[4], pl[5]);
            pal[kc][3] = packh2(pl[6], pl[7]);
        }

        // ---- O += P V (2-term), V via ldmatrix.trans ----
#pragma unroll
        for (int p = 0; p < 4; p++) {
#pragma unroll
            for (int kc = 0; kc < 4; kc++) {
                const uint32_t vb = st + TILEA
                                  + (uint32_t)(kc * 16 + (lane & 15)) * ROWAB
                                  + (uint32_t)(p * 32) + ((lane >> 4) << 4);
                uint32_t v0, v1, v2, v3;
                ldsm_x4t(v0, v1, v2, v3, vb);
                uint32_t bv0[2] = {v0, v1}, bv1[2] = {v2, v3};
                mma16816h(oacc[2*p+0], pah[kc], bv0);
                mma16816h(oacc[2*p+1], pah[kc], bv1);
                mma16816h(oacc[2*p+0], pal[kc], bv0);
                mma16816h(oacc[2*p+1], pal[kc], bv1);
            }
        }
        __syncthreads();   // protect stage from next issue
    }

    // ---- epilogue: normalize, split to fp16 hi/lo, write [B,S,DM] ----
    const float invA = (lA > 0.f) ? (1.f / lA) : 0.f;
    const float invB = (lB > 0.f) ? (1.f / lB) : 0.f;
    const size_t rowA = (size_t)(b * SS + qrA) * DM + h * 64;
    const size_t rowB = (size_t)(b * SS + qrB) * DM + h * 64;
#pragma unroll
    for (int j = 0; j < 8; j++) {
        const int n = j * 8 + t * 2;
        float x0 = oacc[j][0] * invA, x1 = oacc[j][1] * invA;
        float y0 = oacc[j][2] * invB, y1 = oacc[j][3] * invB;
        __half hx0 = __float2half(x0), hx1 = __float2half(x1);
        __half hy0 = __float2half(y0), hy1 = __float2half(y1);
        __half2 HA{hx0, hx1}, HB{hy0, hy1};
        *(uint32_t*)&g_aohi[rowA + n] = *(uint32_t*)&HA;
        *(uint32_t*)&g_aohi[rowB + n] = *(uint32_t*)&HB;
        *(uint32_t*)&g_aolo[rowA + n] =
            packh2(x0 - __half2float(hx0), x1 - __half2float(hx1));
        *(uint32_t*)&g_aolo[rowB + n] =
            packh2(y0 - __half2float(hy0), y1 - __half2float(hy1));
    }
}

// ---------------------------------------------------------------------------
extern "C" void kernel_launch(void* const* d_in, const int* in_sizes, int n_in,
                              void* d_out, int out_size)
{
    (void)in_sizes; (void)n_in; (void)out_size;
    const float* x   = (const float*)d_in[0];
    const int*   pad = (const int*)  d_in[1];
    const float* Wq  = (const float*)d_in[2];
    const float* bq  = (const float*)d_in[3];
    const float* Wk  = (const float*)d_in[4];
    const float* bk  = (const float*)d_in[5];
    const float* Wv  = (const float*)d_in[6];
    const float* bv  = (const float*)d_in[7];
    const float* Wo  = (const float*)d_in[8];
    const float* bo  = (const float*)d_in[9];
    float* out = (float*)d_out;

    __half *xhi, *xlo, *wq16, *aohi, *aolo, *qhi, *qlo, *k16, *v16;
    cudaGetSymbolAddress((void**)&xhi, g_xhi);
    cudaGetSymbolAddress((void**)&xlo, g_xlo);
    cudaGetSymbolAddress((void**)&wq16, g_w);
    cudaGetSymbolAddress((void**)&aohi, g_aohi);
    cudaGetSymbolAddress((void**)&aolo, g_aolo);
    cudaGetSymbolAddress((void**)&qhi, g_qhi);
    cudaGetSymbolAddress((void**)&qlo, g_qlo);
    cudaGetSymbolAddress((void**)&k16, g_k);
    cudaGetSymbolAddress((void**)&v16, g_v);

    cudaFuncSetAttribute(mma_gemm_kernel<1>,
                         cudaFuncAttributeMaxDynamicSharedMemorySize, GSMEM);
    cudaFuncSetAttribute(mma_gemm_kernel<0>,
                         cudaFuncAttributeMaxDynamicSharedMemorySize, GSMEM);
    cudaFuncSetAttribute(mma_flash_kernel,
                         cudaFuncAttributeMaxDynamicSharedMemorySize, ASMEM);

    const int NX4 = MROWS * DM / 4;
    const int NW4 = DM * DM / 4;

    // 1) fp16 split of x; fp16 quantize of weights
    split_kernel<<<(NX4 + 255) / 256, 256>>>(x, xhi, xlo, NX4);
    quant_kernel<<<dim3((NW4 + 255) / 256, 4), 256>>>(Wq, Wk, Wv, Wo, wq16, NW4);

    // 2) QKV projection -> Q hi/lo, K, V (fp16) in [B,H,S,dk]
    mma_gemm_kernel<1><<<dim3(MROWS/128, DM/128, 3), 256, GSMEM>>>(
        xhi, xlo, wq16, 0, bq, bk, bv, nullptr,
        qhi, qlo, k16, v16);

    // 3) HMMA flash attention -> aohi/aolo [B,S,DM]
    mma_flash_kernel<<<dim3(BB*NH, SS/128), 256, ASMEM>>>(pad);

    // 4) output projection -> d_out (fp32)
    mma_gemm_kernel<0><<<dim3(MROWS/128, DM/128, 1), 256, GSMEM>>>(
        aohi, aolo, wq16, 3, bo, bo, bo, out,
        nullptr, nullptr, nullptr, nullptr);
}

// round 10
// speedup vs baseline: 4.9308x; 1.6658x over previous
#include <cuda_runtime.h>
#include <cuda_fp16.h>
#include <cstdint>

#define DM   1024
#define NH   16
#define DKH  64
#define BB   4
#define SS   2048
#define MROWS (BB*SS)   // 8192

// ---------------- device scratch (allocation-free rule) ----------------
__device__ __half g_x16[MROWS*DM];
__device__ __half g_w[4*DM*DM];
__device__ __half g_q[BB*NH*SS*DKH];
__device__ __half g_k[BB*NH*SS*DKH];
__device__ __half g_v[BB*NH*SS*DKH];
__device__ __half g_ao[MROWS*DM];

// ---------------- PTX helpers (baseline ISA: sm_80-class) ----------------
__device__ __forceinline__ uint32_t smem_u32(const void* p) {
    uint32_t a;
    asm("{ .reg .u64 t; cvta.to.shared.u64 t, %1; cvt.u32.u64 %0, t; }" : "=r"(a) : "l"(p));
    return a;
}
__device__ __forceinline__ void cp16(uint32_t dst, const void* src) {
    asm volatile("cp.async.cg.shared.global [%0], [%1], 16;" :: "r"(dst), "l"(src));
}
__device__ __forceinline__ void cp_commit() {
    asm volatile("cp.async.commit_group;" ::: "memory");
}
template<int N> __device__ __forceinline__ void cp_wait() {
    asm volatile("cp.async.wait_group %0;" :: "n"(N) : "memory");
}
__device__ __forceinline__ void ldsm_x4(uint32_t& r0, uint32_t& r1, uint32_t& r2, uint32_t& r3,
                                        uint32_t addr) {
    asm volatile("ldmatrix.sync.aligned.m8n8.x4.shared.b16 {%0,%1,%2,%3}, [%4];"
                 : "=r"(r0), "=r"(r1), "=r"(r2), "=r"(r3) : "r"(addr));
}
__device__ __forceinline__ void ldsm_x4t(uint32_t& r0, uint32_t& r1, uint32_t& r2, uint32_t& r3,
                                         uint32_t addr) {
    asm volatile("ldmatrix.sync.aligned.m8n8.x4.trans.shared.b16 {%0,%1,%2,%3}, [%4];"
                 : "=r"(r0), "=r"(r1), "=r"(r2), "=r"(r3) : "r"(addr));
}
__device__ __forceinline__ void mma16816h(float* c, const uint32_t* a, const uint32_t* b) {
    asm volatile(
        "mma.sync.aligned.m16n8k16.row.col.f32.f16.f16.f32 "
        "{%0,%1,%2,%3}, {%4,%5,%6,%7}, {%8,%9}, {%0,%1,%2,%3};"
        : "+f"(c[0]), "+f"(c[1]), "+f"(c[2]), "+f"(c[3])
        : "r"(a[0]), "r"(a[1]), "r"(a[2]), "r"(a[3]), "r"(b[0]), "r"(b[1]));
}
__device__ __forceinline__ uint32_t packh2(float a, float b) {
    __half2 h = __floats2half2_rn(a, b);
    return *(uint32_t*)&h;
}

// ---------------------------------------------------------------------------
// quantize fp32 -> fp16 (4 elems/thread)
// ---------------------------------------------------------------------------
__global__ void quantx_kernel(const float* __restrict__ src, __half* __restrict__ dst, int n4)
{
    int i = blockIdx.x * blockDim.x + threadIdx.x;
    if (i < n4) {
        float4 v = *(const float4*)(src + i * 4);
        __half2 H0 = __floats2half2_rn(v.x, v.y);
        __half2 H1 = __floats2half2_rn(v.z, v.w);
        *(uint2*)(dst + i * 4) = make_uint2(*(uint32_t*)&H0, *(uint32_t*)&H1);
    }
}

__global__ void quantw_kernel(const float* __restrict__ s0, const float* __restrict__ s1,
                              const float* __restrict__ s2, const float* __restrict__ s3,
                              __half* __restrict__ dst, int n4)
{
    int i = blockIdx.x * blockDim.x + threadIdx.x;
    const int w = blockIdx.y;
    if (i < n4) {
        const float* src = (w == 0) ? s0 : (w == 1) ? s1 : (w == 2) ? s2 : s3;
        float4 v = *(const float4*)(src + i * 4);
        __half2 H0 = __floats2half2_rn(v.x, v.y);
        __half2 H1 = __floats2half2_rn(v.z, v.w);
        *(uint2*)(dst + (size_t)w * DM * DM + i * 4) =
            make_uint2(*(uint32_t*)&H0, *(uint32_t*)&H1);
    }
}

// ---------------------------------------------------------------------------
// HMMA GEMM (fp16 single-term): C[m,n] = A[m,:]*W[n,:] + bias[n]
// CTA 128x128, BK=32, 256 threads (8 warps 2m x 4n), cp.async double buffer.
// SCATTER=1: fp16 scatter into [B,H,S,dk] (Q/K/V).  SCATTER=0: fp32 [M,DM].
// ---------------------------------------------------------------------------
#define BKG    32
#define NCHK   (DM / BKG)         // 32
#define ROWB   80                 // 32 fp16 (64B) + 16B pad
#define TILEB  (128 * ROWB)       // 10240
#define STAGEB (2 * TILEB)        // A, W
#define GSMEM  (2 * STAGEB)       // 40960

template<int SCATTER>
__global__ void __launch_bounds__(256) mma_gemm_kernel(
    const __half* __restrict__ A, const __half* __restrict__ W, int wbase,
    const float* __restrict__ b0, const float* __restrict__ b1, const float* __restrict__ b2,
    float* __restrict__ Cfp,
    __half* __restrict__ H0, __half* __restrict__ H1, __half* __restrict__ H2)
{
    extern __shared__ char sm[];
    const uint32_t sbase = smem_u32(sm);

    const int tid  = threadIdx.x;
    const int warp = tid >> 5;
    const int lane = tid & 31;

    const int z  = blockIdx.z;
    const float* bias = (z == 0) ? b0 : (z == 1) ? b1 : b2;
    __half* Hc = (z == 0) ? H0 : (z == 1) ? H1 : H2;
    const int m0 = blockIdx.x * 128;
    const int n0 = blockIdx.y * 128;

    const int warp_m = (warp & 1) * 64;
    const int warp_n = (warp >> 1) * 32;

    // loaders: tile = tid>>7 (0:A, 1:W), one row each
    const int ltile = tid >> 7;
    const int lrow  = tid & 127;
    const __half* lsrc = ltile
        ? (W + (size_t)(wbase + z) * DM * DM + (size_t)(n0 + lrow) * DM)
        : (A + (size_t)(m0 + lrow) * DM);
    const uint32_t ldst0 = sbase + ltile * TILEB + lrow * ROWB;

    auto issue_stage = [&](int c, int s) {
        const int k0 = c * BKG;
        const uint32_t d = ldst0 + s * STAGEB;
        const char* p = (const char*)(lsrc + k0);
        cp16(d +  0, p +  0);
        cp16(d + 16, p + 16);
        cp16(d + 32, p + 32);
        cp16(d + 48, p + 48);
    };

    const uint32_t a_off = (uint32_t)(warp_m + (lane & 15)) * ROWB + ((lane >> 4) << 4);
    const uint32_t b_off = (uint32_t)(warp_n + ((lane & 16) >> 1) + (lane & 7)) * ROWB
                         + ((lane & 8) ? 16u : 0u);

    float acc[4][4][4];
#pragma unroll
    for (int i = 0; i < 4; i++)
#pragma unroll
        for (int j = 0; j < 4; j++)
#pragma unroll
            for (int r = 0; r < 4; r++) acc[i][j][r] = 0.f;

    issue_stage(0, 0);
    cp_commit();

    for (int c = 0; c < NCHK; c++) {
        const int s = c & 1;
        if (c + 1 < NCHK) { issue_stage(c + 1, 1 - s); cp_commit(); cp_wait<1>(); }
        else             { cp_wait<0>(); }
        __syncthreads();

        const uint32_t tA = sbase + s * STAGEB;
        const uint32_t tW = tA + TILEB;

#pragma unroll
        for (int ks = 0; ks < 2; ks++) {
            const uint32_t ko = ks * 32;

            uint32_t bw[4][2];
#pragma unroll
            for (int bj = 0; bj < 2; bj++) {
                uint32_t r0, r1, r2, r3;
                ldsm_x4(r0, r1, r2, r3, tW + b_off + bj * (16 * ROWB) + ko);
                bw[bj*2+0][0] = r0; bw[bj*2+0][1] = r1;
                bw[bj*2+1][0] = r2; bw[bj*2+1][1] = r3;
            }

            uint32_t a[4][4];
#pragma unroll
            for (int mi = 0; mi < 4; mi++)
                ldsm_x4(a[mi][0], a[mi][1], a[mi][2], a[mi][3],
                        tA + a_off + mi * (16 * ROWB) + ko);
#pragma unroll
            for (int mi = 0; mi < 4; mi++)
#pragma unroll
                for (int nj = 0; nj < 4; nj++)
                    mma16816h(acc[mi][nj], a[mi], bw[nj]);
        }
        __syncthreads();
    }

    const int g = lane >> 2;
    const int t = lane & 3;
#pragma unroll
    for (int mi = 0; mi < 4; mi++) {
#pragma unroll
        for (int nj = 0; nj < 4; nj++) {
            const int n  = n0 + warp_n + nj * 8 + t * 2;
            const float bx = __ldg(bias + n);
            const float by = __ldg(bias + n + 1);
#pragma unroll
            for (int half = 0; half < 2; half++) {
                const int m = m0 + warp_m + mi * 16 + g + half * 8;
                float vx = acc[mi][nj][half * 2 + 0] + bx;
                float vy = acc[mi][nj][half * 2 + 1] + by;
                if (SCATTER) {
                    const int bidx = m >> 11;
                    const int sidx = m & 2047;
                    const int hh   = n >> 6;
                    const int dc   = n & 63;
                    const size_t idx = ((size_t)((bidx * NH + hh) * SS + sidx) << 6) + dc;
                    *(uint32_t*)&Hc[idx] = packh2(vx, vy);
                } else {
                    *(float2*)&Cfp[(size_t)m * DM + n] = make_float2(vx, vy);
                }
            }
        }
    }
}

// ---------------------------------------------------------------------------
// HMMA flash attention (pure fp16 operands, fp32 accum), causal + pad mask.
// CTA: 128 q rows of one (b,h); K/V chunks of 64; 8 warps x 16 rows.
// ---------------------------------------------------------------------------
#define ROWAB  144               // 64 fp16 (128B) + 16 pad
#define TILEA  (64 * ROWAB)      // 9216
#define STAGEA (2 * TILEA + 256) // K, V + pad ints
#define ASMEM  (2 * STAGEA)      // 37376

__global__ void __launch_bounds__(256) mma_flash_kernel(const int* __restrict__ pad)
{
    extern __shared__ char sm[];
    const uint32_t sbase = smem_u32(sm);

    const int tid  = threadIdx.x;
    const int warp = tid >> 5;
    const int lane = tid & 31;
    const int g = lane >> 2;
    const int t = lane & 3;

    const int bh = blockIdx.x;               // 0..63
    const int qt = 15 - blockIdx.y;          // heavy tiles first
    const int b  = bh >> 4;
    const int h  = bh & 15;
    const int q0 = qt * 128;

    const size_t bhoff = (size_t)bh * SS * DKH;
    const __half* Qq = g_q + bhoff;
    const __half* Kq = g_k + bhoff;
    const __half* Vq = g_v + bhoff;

    // ---- stage Q (two 64-row tiles at stage0) ----
    {
        const int row = tid >> 1;
        const int hlf = tid & 1;
        const __half* src = Qq + (size_t)(q0 + row) * DKH + hlf * 32;
        const uint32_t dst = sbase + (row >> 6) * TILEA + (row & 63) * ROWAB + hlf * 64;
#pragma unroll
        for (int i = 0; i < 4; i++) cp16(dst + i * 16, (const char*)src + i * 16);
    }
    cp_commit();
    cp_wait<0>();
    __syncthreads();

    // ---- Q frags into registers ----
    uint32_t qh[4][4];
    {
        const int wrow = warp * 16 + (lane & 15);
        const uint32_t qb = sbase + (wrow >> 6) * TILEA + (wrow & 63) * ROWAB + ((lane >> 4) << 4);
#pragma unroll
        for (int kc = 0; kc < 4; kc++)
            ldsm_x4(qh[kc][0], qh[kc][1], qh[kc][2], qh[kc][3], qb + kc * 32);
    }
    __syncthreads();   // Q consumed; smem reusable

    float oacc[8][4];
#pragma unroll
    for (int j = 0; j < 8; j++)
#pragma unroll
        for (int r = 0; r < 4; r++) oacc[j][r] = 0.f;
    float mA = -1e30f, mB = -1e30f, lA = 0.f, lB = 0.f;

    const int cmax = 2 * qt + 1;
    const int qrA = q0 + warp * 16 + g;
    const int qrB = qrA + 8;

    auto issue = [&](int c) {
        const int stg = (c + 1) & 1;
        const int tile = tid >> 7;           // 0:K, 1:V
        const int rjob = tid & 127;
        const int row  = rjob >> 1;
        const int hlf  = rjob & 1;
        const __half* src = (tile ? Vq : Kq) + (size_t)(c * 64 + row) * DKH + hlf * 32;
        const uint32_t dst = sbase + stg * STAGEA + tile * TILEA + row * ROWAB + hlf * 64;
#pragma unroll
        for (int i = 0; i < 4; i++) cp16(dst + i * 16, (const char*)src + i * 16);
        if (tid < 16)
            cp16(sbase + stg * STAGEA + 2 * TILEA + tid * 16,
                 (const char*)(pad + b * SS + c * 64) + tid * 16);
    };

    issue(0); cp_commit();

    for (int c = 0; c <= cmax; c++) {
        if (c < cmax) { issue(c + 1); cp_commit(); cp_wait<1>(); }
        else          { cp_wait<0>(); }
        __syncthreads();

        const int stg = (c + 1) & 1;
        const uint32_t st = sbase + stg * STAGEA;
        const int* padsm = (const int*)(sm + (size_t)stg * STAGEA + 2 * TILEA);
        const int kc0 = c * 64;

        // ---- S = Q K^T ----
        float sacc[8][4];
#pragma unroll
        for (int j = 0; j < 8; j++)
#pragma unroll
            for (int r = 0; r < 4; r++) sacc[j][r] = 0.f;

#pragma unroll
        for (int p = 0; p < 4; p++) {
            const uint32_t kb = st + (uint32_t)(p * 16 + ((lane & 16) >> 1) + (lane & 7)) * ROWAB
                              + ((lane & 8) ? 16u : 0u);
#pragma unroll
            for (int kc = 0; kc < 4; kc++) {
                uint32_t k0, k1, k2, k3;
                ldsm_x4(k0, k1, k2, k3, kb + kc * 32);
                uint32_t bk0[2] = {k0, k1}, bk1[2] = {k2, k3};
                mma16816h(sacc[2*p+0], qh[kc], bk0);
                mma16816h(sacc[2*p+1], qh[kc], bk1);
            }
        }

        // ---- masked online softmax ----
        float rmA = -1e30f, rmB = -1e30f;
#pragma unroll
        for (int j = 0; j < 8; j++) {
            const int k0i = kc0 + j * 8 + t * 2;
            const bool pm0 = padsm[j * 8 + t * 2]     != 0;
            const bool pm1 = padsm[j * 8 + t * 2 + 1] != 0;
            float s0 = sacc[j][0] * 0.125f; if (k0i     > qrA || pm0) s0 = -1e30f;
            float s1 = sacc[j][1] * 0.125f; if (k0i + 1 > qrA || pm1) s1 = -1e30f;
            float s2 = sacc[j][2] * 0.125f; if (k0i     > qrB || pm0) s2 = -1e30f;
            float s3 = sacc[j][3] * 0.125f; if (k0i + 1 > qrB || pm1) s3 = -1e30f;
            sacc[j][0] = s0; sacc[j][1] = s1; sacc[j][2] = s2; sacc[j][3] = s3;
            rmA = fmaxf(rmA, fmaxf(s0, s1));
            rmB = fmaxf(rmB, fmaxf(s2, s3));
        }
#pragma unroll
        for (int o = 1; o <= 2; o <<= 1) {
            rmA = fmaxf(rmA, __shfl_xor_sync(0xffffffffu, rmA, o));
            rmB = fmaxf(rmB, __shfl_xor_sync(0xffffffffu, rmB, o));
        }
        const float mnA = fmaxf(mA, rmA);
        const float mnB = fmaxf(mB, rmB);
        const float aAl = __expf(mA - mnA);
        const float aBl = __expf(mB - mnB);
        mA = mnA; mB = mnB;

        float sumA = 0.f, sumB = 0.f;
#pragma unroll
        for (int j = 0; j < 8; j++) {
            float p0 = (sacc[j][0] <= -1e30f) ? 0.f : __expf(sacc[j][0] - mnA);
            float p1 = (sacc[j][1] <= -1e30f) ? 0.f : __expf(sacc[j][1] - mnA);
            float p2 = (sacc[j][2] <= -1e30f) ? 0.f : __expf(sacc[j][2] - mnB);
            float p3 = (sacc[j][3] <= -1e30f) ? 0.f : __expf(sacc[j][3] - mnB);
            sumA += p0 + p1; sumB += p2 + p3;
            sacc[j][0] = p0; sacc[j][1] = p1; sacc[j][2] = p2; sacc[j][3] = p3;
        }
#pragma unroll
        for (int o = 1; o <= 2; o <<= 1) {
            sumA += __shfl_xor_sync(0xffffffffu, sumA, o);
            sumB += __shfl_xor_sync(0xffffffffu, sumB, o);
        }
        lA = lA * aAl + sumA;
        lB = lB * aBl + sumB;
#pragma unroll
        for (int j = 0; j < 8; j++) {
            oacc[j][0] *= aAl; oacc[j][1] *= aAl;
            oacc[j][2] *= aBl; oacc[j][3] *= aBl;
        }

        // ---- P -> fp16 A-frags (register reuse) ----
        uint32_t pah[4][4];
#pragma unroll
        for (int kc = 0; kc < 4; kc++) {
            const int j0 = 2 * kc, j1 = 2 * kc + 1;
            pah[kc][0] = packh2(sacc[j0][0], sacc[j0][1]);
            pah[kc][1] = packh2(sacc[j0][2], sacc[j0][3]);
            pah[kc][2] = packh2(sacc[j1][0], sacc[j1][1]);
            pah[kc][3] = packh2(sacc[j1][2], sacc[j1][3]);
        }

        // ---- O += P V, V via ldmatrix.trans ----
#pragma unroll
        for (int p = 0; p < 4; p++) {
#pragma unroll
            for (int kc = 0; kc < 4; kc++) {
                const uint32_t vb = st + TILEA
                                  + (uint32_t)(kc * 16 + (lane & 15)) * ROWAB
                                  + (uint32_t)(p * 32) + ((lane >> 4) << 4);
                uint32_t v0, v1, v2, v3;
                ldsm_x4t(v0, v1, v2, v3, vb);
                uint32_t bv0[2] = {v0, v1}, bv1[2] = {v2, v3};
                mma16816h(oacc[2*p+0], pah[kc], bv0);
                mma16816h(oacc[2*p+1], pah[kc], bv1);
            }
        }
        __syncthreads();   // protect stage from next issue
    }

    // ---- epilogue: normalize, fp16, write [B,S,DM] ----
    const float invA = (lA > 0.f) ? (1.f / lA) : 0.f;
    const float invB = (lB > 0.f) ? (1.f / lB) : 0.f;
    const size_t rowA = (size_t)(b * SS + qrA) * DM + h * 64;
    const size_t rowB = (size_t)(b * SS + qrB) * DM + h * 64;
#pragma unroll
    for (int j = 0; j < 8; j++) {
        const int n = j * 8 + t * 2;
        *(uint32_t*)&g_ao[rowA + n] = packh2(oacc[j][0] * invA, oacc[j][1] * invA);
        *(uint32_t*)&g_ao[rowB + n] = packh2(oacc[j][2] * invB, oacc[j][3] * invB);
    }
}

// ---------------------------------------------------------------------------
extern "C" void kernel_launch(void* const* d_in, const int* in_sizes, int n_in,
                              void* d_out, int out_size)
{
    (void)in_sizes; (void)n_in; (void)out_size;
    const float* x   = (const float*)d_in[0];
    const int*   pad = (const int*)  d_in[1];
    const float* Wq  = (const float*)d_in[2];
    const float* bq  = (const float*)d_in[3];
    const float* Wk  = (const float*)d_in[4];
    const float* bk  = (const float*)d_in[5];
    const float* Wv  = (const float*)d_in[6];
    const float* bv  = (const float*)d_in[7];
    const float* Wo  = (const float*)d_in[8];
    const float* bo  = (const float*)d_in[9];
    float* out = (float*)d_out;

    __half *x16, *w16, *q16, *k16, *v16, *ao16;
    cudaGetSymbolAddress((void**)&x16, g_x16);
    cudaGetSymbolAddress((void**)&w16, g_w);
    cudaGetSymbolAddress((void**)&q16, g_q);
    cudaGetSymbolAddress((void**)&k16, g_k);
    cudaGetSymbolAddress((void**)&v16, g_v);
    cudaGetSymbolAddress((void**)&ao16, g_ao);

    cudaFuncSetAttribute(mma_gemm_kernel<1>,
                         cudaFuncAttributeMaxDynamicSharedMemorySize, GSMEM);
    cudaFuncSetAttribute(mma_gemm_kernel<0>,
                         cudaFuncAttributeMaxDynamicSharedMemorySize, GSMEM);
    cudaFuncSetAttribute(mma_flash_kernel,
                         cudaFuncAttributeMaxDynamicSharedMemorySize, ASMEM);

    const int NX4 = MROWS * DM / 4;
    const int NW4 = DM * DM / 4;

    // 1) fp16 quantization of x and weights
    quantx_kernel<<<(NX4 + 255) / 256, 256>>>(x, x16, NX4);
    quantw_kernel<<<dim3((NW4 + 255) / 256, 4), 256>>>(Wq, Wk, Wv, Wo, w16, NW4);

    // 2) QKV projection -> fp16 [B,H,S,dk]
    mma_gemm_kernel<1><<<dim3(MROWS/128, DM/128, 3), 256, GSMEM>>>(
        x16, w16, 0, bq, bk, bv, nullptr, q16, k16, v16);

    // 3) HMMA flash attention -> fp16 [B,S,DM]
    mma_flash_kernel<<<dim3(BB*NH, SS/128), 256, ASMEM>>>(pad);

    // 4) output projection -> d_out (fp32)
    mma_gemm_kernel<0><<<dim3(MROWS/128, DM/128, 1), 256, GSMEM>>>(
        ao16, w16, 3, bo, bo, bo, out, nullptr, nullptr, nullptr);
}

// round 11
// speedup vs baseline: 5.0602x; 1.0263x over previous
#include <cuda_runtime.h>
#include <cuda_fp16.h>
#include <cstdint>

#define DM   1024
#define NH   16
#define DKH  64
#define BB   4
#define SS   2048
#define MROWS (BB*SS)   // 8192

// ---------------- device scratch (allocation-free rule) ----------------
__device__ __half g_x16[MROWS*DM];
__device__ __half g_w[4*DM*DM];
__device__ __half g_q[BB*NH*SS*DKH];   // pre-scaled by 1/8
__device__ __half g_k[BB*NH*SS*DKH];
__device__ __half g_v[BB*NH*SS*DKH];
__device__ __half g_ao[MROWS*DM];

// ---------------- PTX helpers (baseline ISA: sm_80-class) ----------------
__device__ __forceinline__ uint32_t smem_u32(const void* p) {
    uint32_t a;
    asm("{ .reg .u64 t; cvta.to.shared.u64 t, %1; cvt.u32.u64 %0, t; }" : "=r"(a) : "l"(p));
    return a;
}
__device__ __forceinline__ void cp16(uint32_t dst, const void* src) {
    asm volatile("cp.async.cg.shared.global [%0], [%1], 16;" :: "r"(dst), "l"(src));
}
__device__ __forceinline__ void cp_commit() {
    asm volatile("cp.async.commit_group;" ::: "memory");
}
template<int N> __device__ __forceinline__ void cp_wait() {
    asm volatile("cp.async.wait_group %0;" :: "n"(N) : "memory");
}
__device__ __forceinline__ void ldsm_x4(uint32_t& r0, uint32_t& r1, uint32_t& r2, uint32_t& r3,
                                        uint32_t addr) {
    asm volatile("ldmatrix.sync.aligned.m8n8.x4.shared.b16 {%0,%1,%2,%3}, [%4];"
                 : "=r"(r0), "=r"(r1), "=r"(r2), "=r"(r3) : "r"(addr));
}
__device__ __forceinline__ void ldsm_x4t(uint32_t& r0, uint32_t& r1, uint32_t& r2, uint32_t& r3,
                                         uint32_t addr) {
    asm volatile("ldmatrix.sync.aligned.m8n8.x4.trans.shared.b16 {%0,%1,%2,%3}, [%4];"
                 : "=r"(r0), "=r"(r1), "=r"(r2), "=r"(r3) : "r"(addr));
}
__device__ __forceinline__ void mma16816h(float* c, const uint32_t* a, const uint32_t* b) {
    asm volatile(
        "mma.sync.aligned.m16n8k16.row.col.f32.f16.f16.f32 "
        "{%0,%1,%2,%3}, {%4,%5,%6,%7}, {%8,%9}, {%0,%1,%2,%3};"
        : "+f"(c[0]), "+f"(c[1]), "+f"(c[2]), "+f"(c[3])
        : "r"(a[0]), "r"(a[1]), "r"(a[2]), "r"(a[3]), "r"(b[0]), "r"(b[1]));
}
__device__ __forceinline__ uint32_t packh2(float a, float b) {
    __half2 h = __floats2half2_rn(a, b);
    return *(uint32_t*)&h;
}

// ---------------------------------------------------------------------------
// combined fp32->fp16 quantization: y=0 -> x (n=NX4), y=1..4 -> W_{y-1} (n=NW4)
// ---------------------------------------------------------------------------
__global__ void quant_all_kernel(const float* __restrict__ x,
                                 const float* __restrict__ w0, const float* __restrict__ w1,
                                 const float* __restrict__ w2, const float* __restrict__ w3,
                                 __half* __restrict__ dx, __half* __restrict__ dw,
                                 int nx4, int nw4)
{
    int i = blockIdx.x * blockDim.x + threadIdx.x;
    const int y = blockIdx.y;
    const float* src;
    __half* dst;
    int n4;
    if (y == 0) { src = x; dst = dx; n4 = nx4; }
    else {
        src = (y == 1) ? w0 : (y == 2) ? w1 : (y == 3) ? w2 : w3;
        dst = dw + (size_t)(y - 1) * DM * DM;
        n4 = nw4;
    }
    if (i < n4) {
        float4 v = *(const float4*)(src + i * 4);
        __half2 H0 = __floats2half2_rn(v.x, v.y);
        __half2 H1 = __floats2half2_rn(v.z, v.w);
        *(uint2*)(dst + i * 4) = make_uint2(*(uint32_t*)&H0, *(uint32_t*)&H1);
    }
}

// ---------------------------------------------------------------------------
// HMMA GEMM (fp16): C[m,n] = A[m,:]*W[n,:] + bias[n]
// SCATTER=1: fp16 scatter into [B,H,S,dk]; z==0 (Q) pre-scaled by 1/8.
// SCATTER=0: fp32 row-major [M,DM].
// ---------------------------------------------------------------------------
#define BKG    32
#define NCHK   (DM / BKG)
#define ROWB   80
#define TILEB  (128 * ROWB)
#define STAGEB (2 * TILEB)
#define GSMEM  (2 * STAGEB)

template<int SCATTER>
__global__ void __launch_bounds__(256) mma_gemm_kernel(
    const __half* __restrict__ A, const __half* __restrict__ W, int wbase,
    const float* __restrict__ b0, const float* __restrict__ b1, const float* __restrict__ b2,
    float* __restrict__ Cfp,
    __half* __restrict__ H0, __half* __restrict__ H1, __half* __restrict__ H2)
{
    extern __shared__ char sm[];
    const uint32_t sbase = smem_u32(sm);

    const int tid  = threadIdx.x;
    const int warp = tid >> 5;
    const int lane = tid & 31;

    const int z  = blockIdx.z;
    const float* bias = (z == 0) ? b0 : (z == 1) ? b1 : b2;
    __half* Hc = (z == 0) ? H0 : (z == 1) ? H1 : H2;
    const float oscale = (SCATTER && z == 0) ? 0.125f : 1.0f;
    const int m0 = blockIdx.x * 128;
    const int n0 = blockIdx.y * 128;

    const int warp_m = (warp & 1) * 64;
    const int warp_n = (warp >> 1) * 32;

    const int ltile = tid >> 7;
    const int lrow  = tid & 127;
    const __half* lsrc = ltile
        ? (W + (size_t)(wbase + z) * DM * DM + (size_t)(n0 + lrow) * DM)
        : (A + (size_t)(m0 + lrow) * DM);
    const uint32_t ldst0 = sbase + ltile * TILEB + lrow * ROWB;

    auto issue_stage = [&](int c, int s) {
        const int k0 = c * BKG;
        const uint32_t d = ldst0 + s * STAGEB;
        const char* p = (const char*)(lsrc + k0);
        cp16(d +  0, p +  0);
        cp16(d + 16, p + 16);
        cp16(d + 32, p + 32);
        cp16(d + 48, p + 48);
    };

    const uint32_t a_off = (uint32_t)(warp_m + (lane & 15)) * ROWB + ((lane >> 4) << 4);
    const uint32_t b_off = (uint32_t)(warp_n + ((lane & 16) >> 1) + (lane & 7)) * ROWB
                         + ((lane & 8) ? 16u : 0u);

    float acc[4][4][4];
#pragma unroll
    for (int i = 0; i < 4; i++)
#pragma unroll
        for (int j = 0; j < 4; j++)
#pragma unroll
            for (int r = 0; r < 4; r++) acc[i][j][r] = 0.f;

    issue_stage(0, 0);
    cp_commit();

    for (int c = 0; c < NCHK; c++) {
        const int s = c & 1;
        if (c + 1 < NCHK) { issue_stage(c + 1, 1 - s); cp_commit(); cp_wait<1>(); }
        else             { cp_wait<0>(); }
        __syncthreads();

        const uint32_t tA = sbase + s * STAGEB;
        const uint32_t tW = tA + TILEB;

#pragma unroll
        for (int ks = 0; ks < 2; ks++) {
            const uint32_t ko = ks * 32;

            uint32_t bw[4][2];
#pragma unroll
            for (int bj = 0; bj < 2; bj++) {
                uint32_t r0, r1, r2, r3;
                ldsm_x4(r0, r1, r2, r3, tW + b_off + bj * (16 * ROWB) + ko);
                bw[bj*2+0][0] = r0; bw[bj*2+0][1] = r1;
                bw[bj*2+1][0] = r2; bw[bj*2+1][1] = r3;
            }

            uint32_t a[4][4];
#pragma unroll
            for (int mi = 0; mi < 4; mi++)
                ldsm_x4(a[mi][0], a[mi][1], a[mi][2], a[mi][3],
                        tA + a_off + mi * (16 * ROWB) + ko);
#pragma unroll
            for (int mi = 0; mi < 4; mi++)
#pragma unroll
                for (int nj = 0; nj < 4; nj++)
                    mma16816h(acc[mi][nj], a[mi], bw[nj]);
        }
        __syncthreads();
    }

    const int g = lane >> 2;
    const int t = lane & 3;
#pragma unroll
    for (int mi = 0; mi < 4; mi++) {
#pragma unroll
        for (int nj = 0; nj < 4; nj++) {
            const int n  = n0 + warp_n + nj * 8 + t * 2;
            const float bx = __ldg(bias + n);
            const float by = __ldg(bias + n + 1);
#pragma unroll
            for (int half = 0; half < 2; half++) {
                const int m = m0 + warp_m + mi * 16 + g + half * 8;
                float vx = acc[mi][nj][half * 2 + 0] + bx;
                float vy = acc[mi][nj][half * 2 + 1] + by;
                if (SCATTER) {
                    const int bidx = m >> 11;
                    const int sidx = m & 2047;
                    const int hh   = n >> 6;
                    const int dc   = n & 63;
                    const size_t idx = ((size_t)((bidx * NH + hh) * SS + sidx) << 6) + dc;
                    *(uint32_t*)&Hc[idx] = packh2(vx * oscale, vy * oscale);
                } else {
                    *(float2*)&Cfp[(size_t)m * DM + n] = make_float2(vx, vy);
                }
            }
        }
    }
}

// ---------------------------------------------------------------------------
// HMMA flash attention, fast-path for fully unmasked chunks.
// CTA: 128 q rows of one (b,h); K/V chunks of 64; 8 warps x 16 rows.
// Q is pre-scaled by 1/8 so S needs no scaling.
// ---------------------------------------------------------------------------
#define ROWAB  144
#define TILEA  (64 * ROWAB)
#define STAGEA (2 * TILEA + 256)
#define ASMEM  (2 * STAGEA)

__global__ void __launch_bounds__(256) mma_flash_kernel(const int* __restrict__ pad)
{
    extern __shared__ char sm[];
    const uint32_t sbase = smem_u32(sm);

    const int tid  = threadIdx.x;
    const int warp = tid >> 5;
    const int lane = tid & 31;
    const int g = lane >> 2;
    const int t = lane & 3;

    const int bh = blockIdx.x;
    const int qt = 15 - blockIdx.y;          // heavy tiles first
    const int b  = bh >> 4;
    const int h  = bh & 15;
    const int q0 = qt * 128;

    const size_t bhoff = (size_t)bh * SS * DKH;
    const __half* Qq = g_q + bhoff;
    const __half* Kq = g_k + bhoff;
    const __half* Vq = g_v + bhoff;

    // ---- stage Q ----
    {
        const int row = tid >> 1;
        const int hlf = tid & 1;
        const __half* src = Qq + (size_t)(q0 + row) * DKH + hlf * 32;
        const uint32_t dst = sbase + (row >> 6) * TILEA + (row & 63) * ROWAB + hlf * 64;
#pragma unroll
        for (int i = 0; i < 4; i++) cp16(dst + i * 16, (const char*)src + i * 16);
    }
    cp_commit();
    cp_wait<0>();
    __syncthreads();

    uint32_t qh[4][4];
    {
        const int wrow = warp * 16 + (lane & 15);
        const uint32_t qb = sbase + (wrow >> 6) * TILEA + (wrow & 63) * ROWAB + ((lane >> 4) << 4);
#pragma unroll
        for (int kc = 0; kc < 4; kc++)
            ldsm_x4(qh[kc][0], qh[kc][1], qh[kc][2], qh[kc][3], qb + kc * 32);
    }
    __syncthreads();

    float oacc[8][4];
#pragma unroll
    for (int j = 0; j < 8; j++)
#pragma unroll
        for (int r = 0; r < 4; r++) oacc[j][r] = 0.f;
    float mA = -1e30f, mB = -1e30f, lA = 0.f, lB = 0.f;

    const int cmax = 2 * qt + 1;
    const int qrA = q0 + warp * 16 + g;
    const int qrB = qrA + 8;
    const int wmin = q0 + warp * 16;          // min q row in this warp

    auto issue = [&](int c) {
        const int stg = (c + 1) & 1;
        const int tile = tid >> 7;
        const int rjob = tid & 127;
        const int row  = rjob >> 1;
        const int hlf  = rjob & 1;
        const __half* src = (tile ? Vq : Kq) + (size_t)(c * 64 + row) * DKH + hlf * 32;
        const uint32_t dst = sbase + stg * STAGEA + tile * TILEA + row * ROWAB + hlf * 64;
#pragma unroll
        for (int i = 0; i < 4; i++) cp16(dst + i * 16, (const char*)src + i * 16);
        if (tid < 16)
            cp16(sbase + stg * STAGEA + 2 * TILEA + tid * 16,
                 (const char*)(pad + b * SS + c * 64) + tid * 16);
    };

    issue(0); cp_commit();

    for (int c = 0; c <= cmax; c++) {
        if (c < cmax) { issue(c + 1); cp_commit(); cp_wait<1>(); }
        else          { cp_wait<0>(); }
        __syncthreads();

        const int stg = (c + 1) & 1;
        const uint32_t st = sbase + stg * STAGEA;
        const int* padsm = (const int*)(sm + (size_t)stg * STAGEA + 2 * TILEA);
        const int kc0 = c * 64;

        // ---- S = Q K^T ----
        float sacc[8][4];
#pragma unroll
        for (int j = 0; j < 8; j++)
#pragma unroll
            for (int r = 0; r < 4; r++) sacc[j][r] = 0.f;

#pragma unroll
        for (int p = 0; p < 4; p++) {
            const uint32_t kb = st + (uint32_t)(p * 16 + ((lane & 16) >> 1) + (lane & 7)) * ROWAB
                              + ((lane & 8) ? 16u : 0u);
#pragma unroll
            for (int kc = 0; kc < 4; kc++) {
                uint32_t k0, k1, k2, k3;
                ldsm_x4(k0, k1, k2, k3, kb + kc * 32);
                uint32_t bk0[2] = {k0, k1}, bk1[2] = {k2, k3};
                mma16816h(sacc[2*p+0], qh[kc], bk0);
                mma16816h(sacc[2*p+1], qh[kc], bk1);
            }
        }

        // ---- pad detection (warp-uniform) ----
        const int padv = padsm[2 * lane] | padsm[2 * lane + 1];
        const bool anypad = __ballot_sync(0xffffffffu, padv != 0) != 0u;
        const bool fast = (kc0 + 63 <= wmin) && !anypad;

        float rmA = -1e30f, rmB = -1e30f;
        if (fast) {
#pragma unroll
            for (int j = 0; j < 8; j++) {
                rmA = fmaxf(rmA, fmaxf(sacc[j][0], sacc[j][1]));
                rmB = fmaxf(rmB, fmaxf(sacc[j][2], sacc[j][3]));
            }
        } else {
#pragma unroll
            for (int j = 0; j < 8; j++) {
                const int k0i = kc0 + j * 8 + t * 2;
                const bool pm0 = padsm[j * 8 + t * 2]     != 0;
                const bool pm1 = padsm[j * 8 + t * 2 + 1] != 0;
                float s0 = sacc[j][0]; if (k0i     > qrA || pm0) s0 = -1e30f;
                float s1 = sacc[j][1]; if (k0i + 1 > qrA || pm1) s1 = -1e30f;
                float s2 = sacc[j][2]; if (k0i     > qrB || pm0) s2 = -1e30f;
                float s3 = sacc[j][3]; if (k0i + 1 > qrB || pm1) s3 = -1e30f;
                sacc[j][0] = s0; sacc[j][1] = s1; sacc[j][2] = s2; sacc[j][3] = s3;
                rmA = fmaxf(rmA, fmaxf(s0, s1));
                rmB = fmaxf(rmB, fmaxf(s2, s3));
            }
        }
#pragma unroll
        for (int o = 1; o <= 2; o <<= 1) {
            rmA = fmaxf(rmA, __shfl_xor_sync(0xffffffffu, rmA, o));
            rmB = fmaxf(rmB, __shfl_xor_sync(0xffffffffu, rmB, o));
        }
        const float mnA = fmaxf(mA, rmA);
        const float mnB = fmaxf(mB, rmB);
        const float aAl = __expf(mA - mnA);
        const float aBl = __expf(mB - mnB);
        mA = mnA; mB = mnB;

        float sumA = 0.f, sumB = 0.f;
        if (fast) {
#pragma unroll
            for (int j = 0; j < 8; j++) {
                float p0 = __expf(sacc[j][0] - mnA);
                float p1 = __expf(sacc[j][1] - mnA);
                float p2 = __expf(sacc[j][2] - mnB);
                float p3 = __expf(sacc[j][3] - mnB);
                sumA += p0 + p1; sumB += p2 + p3;
                sacc[j][0] = p0; sacc[j][1] = p1; sacc[j][2] = p2; sacc[j][3] = p3;
            }
        } else {
#pragma unroll
            for (int j = 0; j < 8; j++) {
                float p0 = (sacc[j][0] <= -1e30f) ? 0.f : __expf(sacc[j][0] - mnA);
                float p1 = (sacc[j][1] <= -1e30f) ? 0.f : __expf(sacc[j][1] - mnA);
                float p2 = (sacc[j][2] <= -1e30f) ? 0.f : __expf(sacc[j][2] - mnB);
                float p3 = (sacc[j][3] <= -1e30f) ? 0.f : __expf(sacc[j][3] - mnB);
                sumA += p0 + p1; sumB += p2 + p3;
                sacc[j][0] = p0; sacc[j][1] = p1; sacc[j][2] = p2; sacc[j][3] = p3;
            }
        }
#pragma unroll
        for (int o = 1; o <= 2; o <<= 1) {
            sumA += __shfl_xor_sync(0xffffffffu, sumA, o);
            sumB += __shfl_xor_sync(0xffffffffu, sumB, o);
        }
        lA = lA * aAl + sumA;
        lB = lB * aBl + sumB;
#pragma unroll
        for (int j = 0; j < 8; j++) {
            oacc[j][0] *= aAl; oacc[j][1] *= aAl;
            oacc[j][2] *= aBl; oacc[j][3] *= aBl;
        }

        // ---- P -> fp16 A-frags ----
        uint32_t pah[4][4];
#pragma unroll
        for (int kc = 0; kc < 4; kc++) {
            const int j0 = 2 * kc, j1 = 2 * kc + 1;
            pah[kc][0] = packh2(sacc[j0][0], sacc[j0][1]);
            pah[kc][1] = packh2(sacc[j0][2], sacc[j0][3]);
            pah[kc][2] = packh2(sacc[j1][0], sacc[j1][1]);
            pah[kc][3] = packh2(sacc[j1][2], sacc[j1][3]);
        }

        // ---- O += P V ----
#pragma unroll
        for (int p = 0; p < 4; p++) {
#pragma unroll
            for (int kc = 0; kc < 4; kc++) {
                const uint32_t vb = st + TILEA
                                  + (uint32_t)(kc * 16 + (lane & 15)) * ROWAB
                                  + (uint32_t)(p * 32) + ((lane >> 4) << 4);
                uint32_t v0, v1, v2, v3;
                ldsm_x4t(v0, v1, v2, v3, vb);
                uint32_t bv0[2] = {v0, v1}, bv1[2] = {v2, v3};
                mma16816h(oacc[2*p+0], pah[kc], bv0);
                mma16816h(oacc[2*p+1], pah[kc], bv1);
            }
        }
        __syncthreads();
    }

    // ---- epilogue ----
    const float invA = (lA > 0.f) ? (1.f / lA) : 0.f;
    const float invB = (lB > 0.f) ? (1.f / lB) : 0.f;
    const size_t rowA = (size_t)(b * SS + qrA) * DM + h * 64;
    const size_t rowB = (size_t)(b * SS + qrB) * DM + h * 64;
#pragma unroll
    for (int j = 0; j < 8; j++) {
        const int n = j * 8 + t * 2;
        *(uint32_t*)&g_ao[rowA + n] = packh2(oacc[j][0] * invA, oacc[j][1] * invA);
        *(uint32_t*)&g_ao[rowB + n] = packh2(oacc[j][2] * invB, oacc[j][3] * invB);
    }
}

// ---------------------------------------------------------------------------
extern "C" void kernel_launch(void* const* d_in, const int* in_sizes, int n_in,
                              void* d_out, int out_size)
{
    (void)in_sizes; (void)n_in; (void)out_size;
    const float* x   = (const float*)d_in[0];
    const int*   pad = (const int*)  d_in[1];
    const float* Wq  = (const float*)d_in[2];
    const float* bq  = (const float*)d_in[3];
    const float* Wk  = (const float*)d_in[4];
    const float* bk  = (const float*)d_in[5];
    const float* Wv  = (const float*)d_in[6];
    const float* bv  = (const float*)d_in[7];
    const float* Wo  = (const float*)d_in[8];
    const float* bo  = (const float*)d_in[9];
    float* out = (float*)d_out;

    __half *x16, *w16, *q16, *k16, *v16, *ao16;
    cudaGetSymbolAddress((void**)&x16, g_x16);
    cudaGetSymbolAddress((void**)&w16, g_w);
    cudaGetSymbolAddress((void**)&q16, g_q);
    cudaGetSymbolAddress((void**)&k16, g_k);
    cudaGetSymbolAddress((void**)&v16, g_v);
    cudaGetSymbolAddress((void**)&ao16, g_ao);

    cudaFuncSetAttribute(mma_gemm_kernel<1>,
                         cudaFuncAttributeMaxDynamicSharedMemorySize, GSMEM);
    cudaFuncSetAttribute(mma_gemm_kernel<0>,
                         cudaFuncAttributeMaxDynamicSharedMemorySize, GSMEM);
    cudaFuncSetAttribute(mma_flash_kernel,
                         cudaFuncAttributeMaxDynamicSharedMemorySize, ASMEM);

    const int NX4 = MROWS * DM / 4;
    const int NW4 = DM * DM / 4;

    // 1) fp16 quantization of x + all weights, single launch
    quant_all_kernel<<<dim3((NX4 + 255) / 256, 5), 256>>>(
        x, Wq, Wk, Wv, Wo, x16, w16, NX4, NW4);

    // 2) QKV projection -> fp16 [B,H,S,dk]  (Q pre-scaled by 1/8)
    mma_gemm_kernel<1><<<dim3(MROWS/128, DM/128, 3), 256, GSMEM>>>(
        x16, w16, 0, bq, bk, bv, nullptr, q16, k16, v16);

    // 3) HMMA flash attention -> fp16 [B,S,DM]
    mma_flash_kernel<<<dim3(BB*NH, SS/128), 256, ASMEM>>>(pad);

    // 4) output projection -> d_out (fp32)
    mma_gemm_kernel<0><<<dim3(MROWS/128, DM/128, 1), 256, GSMEM>>>(
        ao16, w16, 3, bo, bo, bo, out, nullptr, nullptr, nullptr);
}

// round 15
// speedup vs baseline: 5.1558x; 1.0189x over previous
#include <cuda_runtime.h>
#include <cuda_fp16.h>
#include <cstdint>

#define DM   1024
#define NH   16
#define DKH  64
#define BB   4
#define SS   2048
#define MROWS (BB*SS)   // 8192

// ---------------- device scratch (allocation-free rule) ----------------
__device__ __half g_x16[MROWS*DM];
__device__ __half g_w[4*DM*DM];
__device__ __half g_q[BB*NH*SS*DKH];   // pre-scaled by 1/8
__device__ __half g_k[BB*NH*SS*DKH];
__device__ __half g_v[BB*NH*SS*DKH];
__device__ __half g_ao[MROWS*DM];

// ---------------- PTX helpers (baseline ISA: sm_80-class) ----------------
__device__ __forceinline__ uint32_t smem_u32(const void* p) {
    uint32_t a;
    asm("{ .reg .u64 t; cvta.to.shared.u64 t, %1; cvt.u32.u64 %0, t; }" : "=r"(a) : "l"(p));
    return a;
}
__device__ __forceinline__ void cp16(uint32_t dst, const void* src) {
    asm volatile("cp.async.cg.shared.global [%0], [%1], 16;" :: "r"(dst), "l"(src));
}
__device__ __forceinline__ void cp_commit() {
    asm volatile("cp.async.commit_group;" ::: "memory");
}
template<int N> __device__ __forceinline__ void cp_wait() {
    asm volatile("cp.async.wait_group %0;" :: "n"(N) : "memory");
}
__device__ __forceinline__ void cp_wait_rem(int rem) {
    if (rem >= 2)      cp_wait<2>();
    else if (rem == 1) cp_wait<1>();
    else               cp_wait<0>();
}
__device__ __forceinline__ void ldsm_x4(uint32_t& r0, uint32_t& r1, uint32_t& r2, uint32_t& r3,
                                        uint32_t addr) {
    asm volatile("ldmatrix.sync.aligned.m8n8.x4.shared.b16 {%0,%1,%2,%3}, [%4];"
                 : "=r"(r0), "=r"(r1), "=r"(r2), "=r"(r3) : "r"(addr));
}
__device__ __forceinline__ void ldsm_x4t(uint32_t& r0, uint32_t& r1, uint32_t& r2, uint32_t& r3,
                                         uint32_t addr) {
    asm volatile("ldmatrix.sync.aligned.m8n8.x4.trans.shared.b16 {%0,%1,%2,%3}, [%4];"
                 : "=r"(r0), "=r"(r1), "=r"(r2), "=r"(r3) : "r"(addr));
}
__device__ __forceinline__ void mma16816h(float* c, const uint32_t* a, const uint32_t* b) {
    asm volatile(
        "mma.sync.aligned.m16n8k16.row.col.f32.f16.f16.f32 "
        "{%0,%1,%2,%3}, {%4,%5,%6,%7}, {%8,%9}, {%0,%1,%2,%3};"
        : "+f"(c[0]), "+f"(c[1]), "+f"(c[2]), "+f"(c[3])
        : "r"(a[0]), "r"(a[1]), "r"(a[2]), "r"(a[3]), "r"(b[0]), "r"(b[1]));
}
__device__ __forceinline__ uint32_t packh2(float a, float b) {
    __half2 h = __floats2half2_rn(a, b);
    return *(uint32_t*)&h;
}

// ---------------------------------------------------------------------------
// combined fp32->fp16 quantization: y=0 -> x (n=NX4), y=1..4 -> W_{y-1} (n=NW4)
// ---------------------------------------------------------------------------
__global__ void quant_all_kernel(const float* __restrict__ x,
                                 const float* __restrict__ w0, const float* __restrict__ w1,
                                 const float* __restrict__ w2, const float* __restrict__ w3,
                                 __half* __restrict__ dx, __half* __restrict__ dw,
                                 int nx4, int nw4)
{
    int i = blockIdx.x * blockDim.x + threadIdx.x;
    const int y = blockIdx.y;
    const float* src;
    __half* dst;
    int n4;
    if (y == 0) { src = x; dst = dx; n4 = nx4; }
    else {
        src = (y == 1) ? w0 : (y == 2) ? w1 : (y == 3) ? w2 : w3;
        dst = dw + (size_t)(y - 1) * DM * DM;
        n4 = nw4;
    }
    if (i < n4) {
        float4 v = *(const float4*)(src + i * 4);
        __half2 H0 = __floats2half2_rn(v.x, v.y);
        __half2 H1 = __floats2half2_rn(v.z, v.w);
        *(uint2*)(dst + i * 4) = make_uint2(*(uint32_t*)&H0, *(uint32_t*)&H1);
    }
}

// ---------------------------------------------------------------------------
// HMMA GEMM (fp16): C[m,n] = A[m,:]*W[n,:] + bias[n]
// 4-stage cp.async ring, ONE barrier per k-chunk.
// SCATTER=1: fp16 scatter into [B,H,S,dk]; z==0 (Q) pre-scaled by 1/8.
// SCATTER=0: fp32 row-major [M,DM].
// ---------------------------------------------------------------------------
#define BKG    32
#define NCHK   (DM / BKG)         // 32
#define ROWB   80
#define TILEB  (128 * ROWB)
#define STAGEB (2 * TILEB)        // A, W
#define NSTG   4
#define GSMEM  (NSTG * STAGEB)    // 81920

template<int SCATTER>
__global__ void __launch_bounds__(256) mma_gemm_kernel(
    const __half* __restrict__ A, const __half* __restrict__ W, int wbase,
    const float* __restrict__ b0, const float* __restrict__ b1, const float* __restrict__ b2,
    float* __restrict__ Cfp,
    __half* __restrict__ H0, __half* __restrict__ H1, __half* __restrict__ H2)
{
    extern __shared__ char sm[];
    const uint32_t sbase = smem_u32(sm);

    const int tid  = threadIdx.x;
    const int warp = tid >> 5;
    const int lane = tid & 31;

    const int z  = blockIdx.z;
    const float* bias = (z == 0) ? b0 : (z == 1) ? b1 : b2;
    __half* Hc = (z == 0) ? H0 : (z == 1) ? H1 : H2;
    const float oscale = (SCATTER && z == 0) ? 0.125f : 1.0f;
    const int m0 = blockIdx.x * 128;
    const int n0 = blockIdx.y * 128;

    const int warp_m = (warp & 1) * 64;
    const int warp_n = (warp >> 1) * 32;

    const int ltile = tid >> 7;
    const int lrow  = tid & 127;
    const __half* lsrc = ltile
        ? (W + (size_t)(wbase + z) * DM * DM + (size_t)(n0 + lrow) * DM)
        : (A + (size_t)(m0 + lrow) * DM);
    const uint32_t ldst0 = sbase + ltile * TILEB + lrow * ROWB;

    auto issue_stage = [&](int c) {
        const int s = c & (NSTG - 1);
        const int k0 = c * BKG;
        const uint32_t d = ldst0 + s * STAGEB;
        const char* p = (const char*)(lsrc + k0);
        cp16(d +  0, p +  0);
        cp16(d + 16, p + 16);
        cp16(d + 32, p + 32);
        cp16(d + 48, p + 48);
        cp_commit();
    };

    const uint32_t a_off = (uint32_t)(warp_m + (lane & 15)) * ROWB + ((lane >> 4) << 4);
    const uint32_t b_off = (uint32_t)(warp_n + ((lane & 16) >> 1) + (lane & 7)) * ROWB
                         + ((lane & 8) ? 16u : 0u);

    float acc[4][4][4];
#pragma unroll
    for (int i = 0; i < 4; i++)
#pragma unroll
        for (int j = 0; j < 4; j++)
#pragma unroll
            for (int r = 0; r < 4; r++) acc[i][j][r] = 0.f;

    issue_stage(0);
    issue_stage(1);
    issue_stage(2);

    for (int c = 0; c < NCHK; c++) {
        cp_wait_rem(NCHK - 1 - c);
        __syncthreads();                      // all warps done with chunk c-1
        if (c + 3 < NCHK) issue_stage(c + 3); // overwrites stage (c-1)&3 — safe

        const uint32_t tA = sbase + (c & (NSTG - 1)) * STAGEB;
        const uint32_t tW = tA + TILEB;

#pragma unroll
        for (int ks = 0; ks < 2; ks++) {
            const uint32_t ko = ks * 32;

            uint32_t bw[4][2];
#pragma unroll
            for (int bj = 0; bj < 2; bj++) {
                uint32_t r0, r1, r2, r3;
                ldsm_x4(r0, r1, r2, r3, tW + b_off + bj * (16 * ROWB) + ko);
                bw[bj*2+0][0] = r0; bw[bj*2+0][1] = r1;
                bw[bj*2+1][0] = r2; bw[bj*2+1][1] = r3;
            }

            uint32_t a[4][4];
#pragma unroll
            for (int mi = 0; mi < 4; mi++)
                ldsm_x4(a[mi][0], a[mi][1], a[mi][2], a[mi][3],
                        tA + a_off + mi * (16 * ROWB) + ko);
#pragma unroll
            for (int mi = 0; mi < 4; mi++)
#pragma unroll
                for (int nj = 0; nj < 4; nj++)
                    mma16816h(acc[mi][nj], a[mi], bw[nj]);
        }
    }

    const int g = lane >> 2;
    const int t = lane & 3;
#pragma unroll
    for (int mi = 0; mi < 4; mi++) {
#pragma unroll
        for (int nj = 0; nj < 4; nj++) {
            const int n  = n0 + warp_n + nj * 8 + t * 2;
            const float bx = __ldg(bias + n);
            const float by = __ldg(bias + n + 1);
#pragma unroll
            for (int half = 0; half < 2; half++) {
                const int m = m0 + warp_m + mi * 16 + g + half * 8;
                float vx = acc[mi][nj][half * 2 + 0] + bx;
                float vy = acc[mi][nj][half * 2 + 1] + by;
                if (SCATTER) {
                    const int bidx = m >> 11;
                    const int sidx = m & 2047;
                    const int hh   = n >> 6;
                    const int dc   = n & 63;
                    const size_t idx = ((size_t)((bidx * NH + hh) * SS + sidx) << 6) + dc;
                    *(uint32_t*)&Hc[idx] = packh2(vx * oscale, vy * oscale);
                } else {
                    *(float2*)&Cfp[(size_t)m * DM + n] = make_float2(vx, vy);
                }
            }
        }
    }
}

// ---------------------------------------------------------------------------
// HMMA flash attention, 4-stage K/V ring, one barrier per chunk,
// fast-path for fully unmasked chunks. Q pre-scaled by 1/8.
// ---------------------------------------------------------------------------
#define ROWAB  144
#define TILEA  (64 * ROWAB)
#define STAGEA (2 * TILEA + 256)
#define ANSTG  4
#define ASMEM  (ANSTG * STAGEA)   // 74752

__global__ void __launch_bounds__(256) mma_flash_kernel(const int* __restrict__ pad)
{
    extern __shared__ char sm[];
    const uint32_t sbase = smem_u32(sm);

    const int tid  = threadIdx.x;
    const int warp = tid >> 5;
    const int lane = tid & 31;
    const int g = lane >> 2;
    const int t = lane & 3;

    const int bh = blockIdx.x;
    const int qt = 15 - blockIdx.y;          // heavy tiles first
    const int b  = bh >> 4;
    const int h  = bh & 15;
    const int q0 = qt * 128;

    const size_t bhoff = (size_t)bh * SS * DKH;
    const __half* Qq = g_q + bhoff;
    const __half* Kq = g_k + bhoff;
    const __half* Vq = g_v + bhoff;

    // ---- stage Q into stage-0 region ----
    {
        const int row = tid >> 1;
        const int hlf = tid & 1;
        const __half* src = Qq + (size_t)(q0 + row) * DKH + hlf * 32;
        const uint32_t dst = sbase + (row >> 6) * TILEA + (row & 63) * ROWAB + hlf * 64;
#pragma unroll
        for (int i = 0; i < 4; i++) cp16(dst + i * 16, (const char*)src + i * 16);
    }
    cp_commit();
    cp_wait<0>();
    __syncthreads();

    uint32_t qh[4][4];
    {
        const int wrow = warp * 16 + (lane & 15);
        const uint32_t qb = sbase + (wrow >> 6) * TILEA + (wrow & 63) * ROWAB + ((lane >> 4) << 4);
#pragma unroll
        for (int kc = 0; kc < 4; kc++)
            ldsm_x4(qh[kc][0], qh[kc][1], qh[kc][2], qh[kc][3], qb + kc * 32);
    }
    __syncthreads();   // Q consumed; ring reusable

    float oacc[8][4];
#pragma unroll
    for (int j = 0; j < 8; j++)
#pragma unroll
        for (int r = 0; r < 4; r++) oacc[j][r] = 0.f;
    float mA = -1e30f, mB = -1e30f, lA = 0.f, lB = 0.f;

    const int cmax = 2 * qt + 1;
    const int qrA = q0 + warp * 16 + g;
    const int qrB = qrA + 8;
    const int wmin = q0 + warp * 16;

    auto issue = [&](int c) {
        const int stg = c & (ANSTG - 1);
        const int tile = tid >> 7;
        const int rjob = tid & 127;
        const int row  = rjob >> 1;
        const int hlf  = rjob & 1;
        const __half* src = (tile ? Vq : Kq) + (size_t)(c * 64 + row) * DKH + hlf * 32;
        const uint32_t dst = sbase + stg * STAGEA + tile * TILEA + row * ROWAB + hlf * 64;
#pragma unroll
        for (int i = 0; i < 4; i++) cp16(dst + i * 16, (const char*)src + i * 16);
        if (tid < 16)
            cp16(sbase + stg * STAGEA + 2 * TILEA + tid * 16,
                 (const char*)(pad + b * SS + c * 64) + tid * 16);
        cp_commit();
    };

    issue(0);
    if (cmax >= 1) issue(1);
    if (cmax >= 2) issue(2);

    for (int c = 0; c <= cmax; c++) {
        cp_wait_rem(cmax - c);
        __syncthreads();                    // all warps done with chunk c-1
        if (c + 3 <= cmax) issue(c + 3);

        const uint32_t st = sbase + (c & (ANSTG - 1)) * STAGEA;
        const int* padsm = (const int*)(sm + (size_t)(c & (ANSTG - 1)) * STAGEA + 2 * TILEA);
        const int kc0 = c * 64;

        // ---- S = Q K^T ----
        float sacc[8][4];
#pragma unroll
        for (int j = 0; j < 8; j++)
#pragma unroll
            for (int r = 0; r < 4; r++) sacc[j][r] = 0.f;

#pragma unroll
        for (int p = 0; p < 4; p++) {
            const uint32_t kb = st + (uint32_t)(p * 16 + ((lane & 16) >> 1) + (lane & 7)) * ROWAB
                              + ((lane & 8) ? 16u : 0u);
#pragma unroll
            for (int kc = 0; kc < 4; kc++) {
                uint32_t k0, k1, k2, k3;
                ldsm_x4(k0, k1, k2, k3, kb + kc * 32);
                uint32_t bk0[2] = {k0, k1}, bk1[2] = {k2, k3};
                mma16816h(sacc[2*p+0], qh[kc], bk0);
                mma16816h(sacc[2*p+1], qh[kc], bk1);
            }
        }

        // ---- pad detection (warp-uniform) ----
        const int padv = padsm[2 * lane] | padsm[2 * lane + 1];
        const bool anypad = __ballot_sync(0xffffffffu, padv != 0) != 0u;
        const bool fast = (kc0 + 63 <= wmin) && !anypad;

        float rmA = -1e30f, rmB = -1e30f;
        if (fast) {
#pragma unroll
            for (int j = 0; j < 8; j++) {
                rmA = fmaxf(rmA, fmaxf(sacc[j][0], sacc[j][1]));
                rmB = fmaxf(rmB, fmaxf(sacc[j][2], sacc[j][3]));
            }
        } else {
#pragma unroll
            for (int j = 0; j < 8; j++) {
                const int k0i = kc0 + j * 8 + t * 2;
                const bool pm0 = padsm[j * 8 + t * 2]     != 0;
                const bool pm1 = padsm[j * 8 + t * 2 + 1] != 0;
                float s0 = sacc[j][0]; if (k0i     > qrA || pm0) s0 = -1e30f;
                float s1 = sacc[j][1]; if (k0i + 1 > qrA || pm1) s1 = -1e30f;
                float s2 = sacc[j][2]; if (k0i     > qrB || pm0) s2 = -1e30f;
                float s3 = sacc[j][3]; if (k0i + 1 > qrB || pm1) s3 = -1e30f;
                sacc[j][0] = s0; sacc[j][1] = s1; sacc[j][2] = s2; sacc[j][3] = s3;
                rmA = fmaxf(rmA, fmaxf(s0, s1));
                rmB = fmaxf(rmB, fmaxf(s2, s3));
            }
        }
#pragma unroll
        for (int o = 1; o <= 2; o <<= 1) {
            rmA = fmaxf(rmA, __shfl_xor_sync(0xffffffffu, rmA, o));
            rmB = fmaxf(rmB, __shfl_xor_sync(0xffffffffu, rmB, o));
        }
        const float mnA = fmaxf(mA, rmA);
        const float mnB = fmaxf(mB, rmB);
        const float aAl = __expf(mA - mnA);
        const float aBl = __expf(mB - mnB);
        mA = mnA; mB = mnB;

        float sumA = 0.f, sumB = 0.f;
        if (fast) {
#pragma unroll
            for (int j = 0; j < 8; j++) {
                float p0 = __expf(sacc[j][0] - mnA);
                float p1 = __expf(sacc[j][1] - mnA);
                float p2 = __expf(sacc[j][2] - mnB);
                float p3 = __expf(sacc[j][3] - mnB);
                sumA += p0 + p1; sumB += p2 + p3;
                sacc[j][0] = p0; sacc[j][1] = p1; sacc[j][2] = p2; sacc[j][3] = p3;
            }
        } else {
#pragma unroll
            for (int j = 0; j < 8; j++) {
                float p0 = (sacc[j][0] <= -1e30f) ? 0.f : __expf(sacc[j][0] - mnA);
                float p1 = (sacc[j][1] <= -1e30f) ? 0.f : __expf(sacc[j][1] - mnA);
                float p2 = (sacc[j][2] <= -1e30f) ? 0.f : __expf(sacc[j][2] - mnB);
                float p3 = (sacc[j][3] <= -1e30f) ? 0.f : __expf(sacc[j][3] - mnB);
                sumA += p0 + p1; sumB += p2 + p3;
                sacc[j][0] = p0; sacc[j][1] = p1; sacc[j][2] = p2; sacc[j][3] = p3;
            }
        }
#pragma unroll
        for (int o = 1; o <= 2; o <<= 1) {
            sumA += __shfl_xor_sync(0xffffffffu, sumA, o);
            sumB += __shfl_xor_sync(0xffffffffu, sumB, o);
        }
        lA = lA * aAl + sumA;
        lB = lB * aBl + sumB;
#pragma unroll
        for (int j = 0; j < 8; j++) {
            oacc[j][0] *= aAl; oacc[j][1] *= aAl;
            oacc[j][2] *= aBl; oacc[j][3] *= aBl;
        }

        // ---- P -> fp16 A-frags ----
        uint32_t pah[4][4];
#pragma unroll
        for (int kc = 0; kc < 4; kc++) {
            const int j0 = 2 * kc, j1 = 2 * kc + 1;
            pah[kc][0] = packh2(sacc[j0][0], sacc[j0][1]);
            pah[kc][1] = packh2(sacc[j0][2], sacc[j0][3]);
            pah[kc][2] = packh2(sacc[j1][0], sacc[j1][1]);
            pah[kc][3] = packh2(sacc[j1][2], sacc[j1][3]);
        }

        // ---- O += P V ----
#pragma unroll
        for (int p = 0; p < 4; p++) {
#pragma unroll
            for (int kc = 0; kc < 4; kc++) {
                const uint32_t vb = st + TILEA
                                  + (uint32_t)(kc * 16 + (lane & 15)) * ROWAB
                                  + (uint32_t)(p * 32) + ((lane >> 4) << 4);
                uint32_t v0, v1, v2, v3;
                ldsm_x4t(v0, v1, v2, v3, vb);
                uint32_t bv0[2] = {v0, v1}, bv1[2] = {v2, v3};
                mma16816h(oacc[2*p+0], pah[kc], bv0);
                mma16816h(oacc[2*p+1], pah[kc], bv1);
            }
        }
    }

    // ---- epilogue ----
    const float invA = (lA > 0.f) ? (1.f / lA) : 0.f;
    const float invB = (lB > 0.f) ? (1.f / lB) : 0.f;
    const size_t rowA = (size_t)(b * SS + qrA) * DM + h * 64;
    const size_t rowB = (size_t)(b * SS + qrB) * DM + h * 64;
#pragma unroll
    for (int j = 0; j < 8; j++) {
        const int n = j * 8 + t * 2;
        *(uint32_t*)&g_ao[rowA + n] = packh2(oacc[j][0] * invA, oacc[j][1] * invA);
        *(uint32_t*)&g_ao[rowB + n] = packh2(oacc[j][2] * invB, oacc[j][3] * invB);
    }
}

// ---------------------------------------------------------------------------
extern "C" void kernel_launch(void* const* d_in, const int* in_sizes, int n_in,
                              void* d_out, int out_size)
{
    (void)in_sizes; (void)n_in; (void)out_size;
    const float* x   = (const float*)d_in[0];
    const int*   pad = (const int*)  d_in[1];
    const float* Wq  = (const float*)d_in[2];
    const float* bq  = (const float*)d_in[3];
    const float* Wk  = (const float*)d_in[4];
    const float* bk  = (const float*)d_in[5];
    const float* Wv  = (const float*)d_in[6];
    const float* bv  = (const float*)d_in[7];
    const float* Wo  = (const float*)d_in[8];
    const float* bo  = (const float*)d_in[9];
    float* out = (float*)d_out;

    __half *x16, *w16, *q16, *k16, *v16, *ao16;
    cudaGetSymbolAddress((void**)&x16, g_x16);
    cudaGetSymbolAddress((void**)&w16, g_w);
    cudaGetSymbolAddress((void**)&q16, g_q);
    cudaGetSymbolAddress((void**)&k16, g_k);
    cudaGetSymbolAddress((void**)&v16, g_v);
    cudaGetSymbolAddress((void**)&ao16, g_ao);

    cudaFuncSetAttribute(mma_gemm_kernel<1>,
                         cudaFuncAttributeMaxDynamicSharedMemorySize, GSMEM);
    cudaFuncSetAttribute(mma_gemm_kernel<0>,
                         cudaFuncAttributeMaxDynamicSharedMemorySize, GSMEM);
    cudaFuncSetAttribute(mma_flash_kernel,
                         cudaFuncAttributeMaxDynamicSharedMemorySize, ASMEM);

    const int NX4 = MROWS * DM / 4;
    const int NW4 = DM * DM / 4;

    // 1) fp16 quantization of x + all weights, single launch
    quant_all_kernel<<<dim3((NX4 + 255) / 256, 5), 256>>>(
        x, Wq, Wk, Wv, Wo, x16, w16, NX4, NW4);

    // 2) QKV projection -> fp16 [B,H,S,dk]  (Q pre-scaled by 1/8)
    mma_gemm_kernel<1><<<dim3(MROWS/128, DM/128, 3), 256, GSMEM>>>(
        x16, w16, 0, bq, bk, bv, nullptr, q16, k16, v16);

    // 3) HMMA flash attention -> fp16 [B,S,DM]
    mma_flash_kernel<<<dim3(BB*NH, SS/128), 256, ASMEM>>>(pad);

    // 4) output projection -> d_out (fp32)
    mma_gemm_kernel<0><<<dim3(MROWS/128, DM/128, 1), 256, GSMEM>>>(
        ao16, w16, 3, bo, bo, bo, out, nullptr, nullptr, nullptr);
}